// round 5
// baseline (speedup 1.0000x reference)
#include <cuda_runtime.h>
#include <cstdint>

#define B_   128
#define T_   64
#define V_   1024
#define TS_  64
#define H_   512
#define NTOK (B_ * T_)      // 8192
#define G3   (3 * H_)       // 1536
#define IN_  (V_ + TS_)     // 1088

typedef unsigned long long ull;

// ---------------- packed fp32x2 helpers (Blackwell) ----------------
__device__ __forceinline__ ull ffma2(ull a, ull b, ull c) {
    ull d;
    asm("fma.rn.f32x2 %0, %1, %2, %3;" : "=l"(d) : "l"(a), "l"(b), "l"(c));
    return d;
}
__device__ __forceinline__ ull dup2(float a) {
    ull d; unsigned u = __float_as_uint(a);
    asm("mov.b64 %0, {%1, %2};" : "=l"(d) : "r"(u), "r"(u));
    return d;
}
__device__ __forceinline__ float2 u2f(ull a) {
    float2 f; unsigned lo, hi;
    asm("mov.b64 {%0, %1}, %2;" : "=r"(lo), "=r"(hi) : "l"(a));
    f.x = __uint_as_float(lo); f.y = __uint_as_float(hi);
    return f;
}
__device__ __forceinline__ float tanhfast(float x) {
    float y; asm("tanh.approx.f32 %0, %1;" : "=f"(y) : "f"(x)); return y;
}

// ---------------- device scratch ----------------
__device__ float g_xg[NTOK * G3];
__device__ float g_coefA[G3];
__device__ float g_coefC[G3];

// ---------------- kernel 0: fold time-embedding into coefficients ----------------
__global__ void coef_kernel(const float* __restrict__ W_time,
                            const float* __restrict__ b_time,
                            const float* __restrict__ W_ih,
                            const float* __restrict__ b_ih)
{
    int g = blockIdx.x * blockDim.x + threadIdx.x;
    if (g >= G3) return;
    const float* wrow = W_ih + (size_t)g * IN_ + V_;
    float a = 0.f, cc = 0.f;
#pragma unroll 8
    for (int j = 0; j < TS_; j++) {
        float wv = wrow[j];
        a  += W_time[j] * wv;
        cc += b_time[j] * wv;
    }
    g_coefA[g] = a;
    g_coefC[g] = cc + b_ih[g];
}

// ---------------- kernel 1: xg = visit_emb @ W_ih[:, :V]^T (+ epilogue) ----------------
#define BM 128
#define BN 128
#define BK 16
#define AST 132

__global__ __launch_bounds__(256, 2)
void gemm_kernel(const float* __restrict__ A,
                 const float* __restrict__ Bw,
                 const float* __restrict__ interval)
{
    __shared__ float As[BK][AST];
    __shared__ float Bs[BK][AST];

    int tid = threadIdx.x;
    int tx = tid & 15;
    int ty = tid >> 4;
    int rowBase = blockIdx.y * BM;
    int colBase = blockIdx.x * BN;

    int lr = tid >> 2;
    int kq = tid & 3;

    ull acc2[8][4];
#pragma unroll
    for (int i = 0; i < 8; i++)
#pragma unroll
        for (int j = 0; j < 4; j++) acc2[i][j] = 0ull;

    const float* Aptr = A  + (size_t)(rowBase + lr) * V_  + kq * 4;
    const float* Bptr = Bw + (size_t)(colBase + lr) * IN_ + kq * 4;

    for (int kt = 0; kt < V_; kt += BK) {
        float4 a0 = *(const float4*)(Aptr + kt);
        float4 a1 = *(const float4*)(Aptr + (size_t)64 * V_ + kt);
        float4 b0 = *(const float4*)(Bptr + kt);
        float4 b1 = *(const float4*)(Bptr + (size_t)64 * IN_ + kt);

        __syncthreads();
        As[kq*4+0][lr] = a0.x; As[kq*4+1][lr] = a0.y; As[kq*4+2][lr] = a0.z; As[kq*4+3][lr] = a0.w;
        As[kq*4+0][lr+64] = a1.x; As[kq*4+1][lr+64] = a1.y; As[kq*4+2][lr+64] = a1.z; As[kq*4+3][lr+64] = a1.w;
        Bs[kq*4+0][lr] = b0.x; Bs[kq*4+1][lr] = b0.y; Bs[kq*4+2][lr] = b0.z; Bs[kq*4+3][lr] = b0.w;
        Bs[kq*4+0][lr+64] = b1.x; Bs[kq*4+1][lr+64] = b1.y; Bs[kq*4+2][lr+64] = b1.z; Bs[kq*4+3][lr+64] = b1.w;
        __syncthreads();

#pragma unroll
        for (int kk = 0; kk < BK; kk++) {
            const float* ap = &As[kk][ty*8];
            float av[8];
            *(float4*)(av+0) = *(const float4*)(ap);
            *(float4*)(av+4) = *(const float4*)(ap + 4);
            const ull* bp = (const ull*)&Bs[kk][tx*8];
            ull bv0 = bp[0], bv1 = bp[1], bv2 = bp[2], bv3 = bp[3];
#pragma unroll
            for (int i = 0; i < 8; i++) {
                ull a2 = dup2(av[i]);
                acc2[i][0] = ffma2(a2, bv0, acc2[i][0]);
                acc2[i][1] = ffma2(a2, bv1, acc2[i][1]);
                acc2[i][2] = ffma2(a2, bv2, acc2[i][2]);
                acc2[i][3] = ffma2(a2, bv3, acc2[i][3]);
            }
        }
    }

    float ai[8], ca[8], cc[8];
#pragma unroll
    for (int i = 0; i < 8; i++) ai[i] = interval[rowBase + ty*8 + i];
#pragma unroll
    for (int j = 0; j < 8; j++) {
        ca[j] = g_coefA[colBase + tx*8 + j];
        cc[j] = g_coefC[colBase + tx*8 + j];
    }
#pragma unroll
    for (int i = 0; i < 8; i++) {
        size_t rbase = (size_t)(rowBase + ty*8 + i) * G3 + colBase + tx*8;
#pragma unroll
        for (int q = 0; q < 2; q++) {
            float2 v0 = u2f(acc2[i][2*q+0]);
            float2 v1 = u2f(acc2[i][2*q+1]);
            float4 o;
            o.x = v0.x + ai[i] * ca[4*q+0] + cc[4*q+0];
            o.y = v0.y + ai[i] * ca[4*q+1] + cc[4*q+1];
            o.z = v1.x + ai[i] * ca[4*q+2] + cc[4*q+2];
            o.w = v1.y + ai[i] * ca[4*q+3] + cc[4*q+3];
            *(float4*)&g_xg[rbase + 4*q] = o;
        }
    }
}

// ---------------- kernel 2: persistent cluster GRU scan, tag-in-data sync ----------------
// 16-CTA cluster, 512 threads. Warp w of CTA c owns units j0=32c+2w, j0+1
// (6 W_hh rows as f32x2 in registers). h state lives in slots[2][512] of
// {f32 h, u32 step_tag} packed in one aligned b64: store is atomic, so a plain
// volatile load that sees tag>=target also sees the matching h. No mbarriers,
// no acquire/release. Double-buffered sets by step parity; safety: every warp
// posts step s only after fully reading set (s-1)&1, and every warp's step-s
// matvec spin covers all 512 slots, so a writer of set (s+1)&1 cannot clobber
// a set still being read.
// Slot permutation: slot(col) = ((col>>2)&3)*128 + (col>>4)*4 + (col&3)
//   => lane l's qq-group (4 cols) is 4 consecutive slots = 2x LDS.128.

__device__ __forceinline__ int hperm(int col) {
    return ((col >> 2) & 3) * 128 + ((col >> 4) << 2) + (col & 3);
}

__global__ void __launch_bounds__(512, 1)
scan_kernel(const float* __restrict__ W_hh,
            const float* __restrict__ b_hh,
            const int*   __restrict__ lens,
            float*       __restrict__ out)
{
    __shared__ ull   hslots[2][512];   // {h, tag} per unit, double-buffered
    __shared__ float stage[32];
    __shared__ float bhh[96];
    __shared__ int   lens_sm[128];

    int tid = threadIdx.x;
    int w = tid >> 5;
    int l = tid & 31;
    uint32_t c;
    asm("mov.u32 %0, %%cluster_ctarank;" : "=r"(c));

    hslots[0][tid] = 0ull;             // h=0, tag=0
    hslots[1][tid] = 0ull;
    if (tid < 128) lens_sm[tid] = lens[tid];
    if (tid < 96) {
        int g = tid >> 5, u = tid & 31;
        bhh[tid] = b_hh[g * H_ + 32 * (int)c + u];
    }
    __syncthreads();
    asm volatile("barrier.cluster.arrive.aligned;" ::: "memory");
    asm volatile("barrier.cluster.wait.aligned;"   ::: "memory");

    // ---- weights to registers (6 rows x 16 cols as 48 f32x2) ----
    int j0 = 32 * (int)c + 2 * w;
    ull W2[6][8];
#pragma unroll
    for (int r = 0; r < 6; r++) {
        int row = (r < 2) ? (j0 + r) : (r < 4) ? (H_ + j0 + r - 2) : (2 * H_ + j0 + r - 4);
        const ull* wp = (const ull*)(W_hh + (size_t)row * H_ + 16 * l);
#pragma unroll
        for (int k = 0; k < 8; k++) W2[r][k] = wp[k];
    }

    uint32_t sbase = (uint32_t)__cvta_generic_to_shared(hslots);
    // remote store address: warp w ships stage[l] (unit 32c+l) to CTA w
    uint32_t ra_store;
    {
        uint32_t la = sbase + (uint32_t)(hperm(32 * (int)c + l) * 8);
        asm("mapa.shared::cluster.u32 %0, %1, %2;" : "=r"(ra_store) : "r"(la), "r"(w));
    }

    unsigned s = 1;
    for (int b = 0; b < B_; b++) {
        int len = lens_sm[b];
        for (int t = 0; t < len; t++) {
            unsigned target = s - 1;
            uint32_t rd_off = ((s - 1) & 1u) * 4096u;

            // xg loads issued now, consumed ~500 cyc later (after reduce)
            float xr = 0.f, xz = 0.f, xn = 0.f;
            if (l < 2) {
                const float* xp = g_xg + (size_t)((b << 6) + t) * G3 + (j0 + l);
                xr = __ldg(xp);
                xz = __ldg(xp + H_);
                xn = __ldg(xp + 2 * H_);
            }

            // ---- matvec: per qq-group spin-load 4 slots, then 12 FFMA2 ----
            ull acc2[6] = {0ull, 0ull, 0ull, 0ull, 0ull, 0ull};
#pragma unroll
            for (int qq = 0; qq < 4; qq++) {
                uint32_t a0 = sbase + rd_off + (uint32_t)((qq * 128 + l * 4) * 8);
                ull u0, u1, u2, u3;
                for (;;) {
                    asm volatile("ld.volatile.shared.v2.b64 {%0,%1}, [%2];"
                                 : "=l"(u0), "=l"(u1) : "r"(a0) : "memory");
                    asm volatile("ld.volatile.shared.v2.b64 {%0,%1}, [%2];"
                                 : "=l"(u2), "=l"(u3) : "r"(a0 + 16) : "memory");
                    unsigned m = min(min((unsigned)(u0 >> 32), (unsigned)(u1 >> 32)),
                                     min((unsigned)(u2 >> 32), (unsigned)(u3 >> 32)));
                    if (m >= target) break;
                }
                ull h01, h23;
                asm("mov.b64 %0, {%1, %2};" : "=l"(h01)
                    : "r"((unsigned)u0), "r"((unsigned)u1));
                asm("mov.b64 %0, {%1, %2};" : "=l"(h23)
                    : "r"((unsigned)u2), "r"((unsigned)u3));
#pragma unroll
                for (int r = 0; r < 6; r++) acc2[r] = ffma2(W2[r][2*qq+0], h01, acc2[r]);
#pragma unroll
                for (int r = 0; r < 6; r++) acc2[r] = ffma2(W2[r][2*qq+1], h23, acc2[r]);
            }
            float acc[6];
#pragma unroll
            for (int r = 0; r < 6; r++) { float2 f = u2f(acc2[r]); acc[r] = f.x + f.y; }

#pragma unroll
            for (int off = 16; off > 0; off >>= 1) {
#pragma unroll
                for (int r = 0; r < 6; r++)
                    acc[r] += __shfl_xor_sync(0xffffffffu, acc[r], off);
            }

            // ---- gates on lanes 0,1 (tanh.approx) ----
            if (l < 2) {
                int bidx = 2 * w + l;
                uint32_t ah = sbase + rd_off + (uint32_t)(hperm(j0 + l) * 8);
                ull hu;
                do {
                    asm volatile("ld.volatile.shared.b64 %0, [%1];"
                                 : "=l"(hu) : "r"(ah) : "memory");
                } while ((unsigned)(hu >> 32) < target);
                float hold = __uint_as_float((unsigned)hu);
                float rr = 0.5f * tanhfast(0.5f * (xr + acc[l]     + bhh[bidx]))      + 0.5f;
                float zz = 0.5f * tanhfast(0.5f * (xz + acc[2 + l] + bhh[32 + bidx])) + 0.5f;
                float nn = tanhfast(xn + rr * (acc[4 + l] + bhh[64 + bidx]));
                stage[bidx] = fmaf(zz, hold - nn, nn);
            }
            __syncthreads();

            // ---- publish: lane l ships {stage[l], s} to CTA w's slot set s&1 ----
            {
                ull v;
                unsigned hu = __float_as_uint(stage[l]);
                asm("mov.b64 %0, {%1, %2};" : "=l"(v) : "r"(hu), "r"(s));
                uint32_t ra = ra_store + (s & 1u) * 4096u;
                asm volatile("st.relaxed.cluster.shared::cluster.b64 [%0], %1;"
                             :: "r"(ra), "l"(v) : "memory");
            }
            s++;
        }

        // hidden after sample b (warp 0): spin per-slot on tag >= s-1
        if (tid < 32) {
            unsigned target = s - 1;
            uint32_t ah = sbase + ((s - 1) & 1u) * 4096u
                        + (uint32_t)(hperm(32 * (int)c + l) * 8);
            ull hu;
            do {
                asm volatile("ld.volatile.shared.b64 %0, [%1];"
                             : "=l"(hu) : "r"(ah) : "memory");
            } while ((unsigned)(hu >> 32) < target);
            out[b * H_ + 32 * (int)c + l] = __uint_as_float((unsigned)hu);
        }
    }

    // keep smem alive while in-flight remote stores land
    asm volatile("barrier.cluster.arrive.aligned;" ::: "memory");
    asm volatile("barrier.cluster.wait.aligned;"   ::: "memory");
}

// ---------------- launcher ----------------
extern "C" void kernel_launch(void* const* d_in, const int* in_sizes, int n_in,
                              void* d_out, int out_size)
{
    const float* visit_emb = (const float*)d_in[0];
    const float* intervals = (const float*)d_in[1];
    const float* W_time    = (const float*)d_in[2];
    const float* b_time    = (const float*)d_in[3];
    const float* W_ih      = (const float*)d_in[4];
    const float* W_hh      = (const float*)d_in[5];
    const float* b_ih      = (const float*)d_in[6];
    const float* b_hh      = (const float*)d_in[7];
    const int*   lens      = (const int*)d_in[8];
    float* out = (float*)d_out;

    coef_kernel<<<(G3 + 255) / 256, 256>>>(W_time, b_time, W_ih, b_ih);

    dim3 ggrid(G3 / BN, NTOK / BM);   // (12, 64)
    gemm_kernel<<<ggrid, 256>>>(visit_emb, W_ih, intervals);

    cudaFuncSetAttribute(scan_kernel, cudaFuncAttributeNonPortableClusterSizeAllowed, 1);

    cudaLaunchConfig_t cfg = {};
    cfg.gridDim  = dim3(16, 1, 1);
    cfg.blockDim = dim3(512, 1, 1);
    cfg.dynamicSmemBytes = 0;
    cfg.stream = 0;
    cudaLaunchAttribute attrs[1];
    attrs[0].id = cudaLaunchAttributeClusterDimension;
    attrs[0].val.clusterDim.x = 16;
    attrs[0].val.clusterDim.y = 1;
    attrs[0].val.clusterDim.z = 1;
    cfg.attrs = attrs;
    cfg.numAttrs = 1;

    cudaLaunchKernelEx(&cfg, scan_kernel, W_hh, b_hh, lens, out);
}

// round 6
// speedup vs baseline: 2.9621x; 2.9621x over previous
#include <cuda_runtime.h>
#include <cstdint>

#define B_   128
#define T_   64
#define V_   1024
#define TS_  64
#define H_   512
#define NTOK (B_ * T_)      // 8192
#define G3   (3 * H_)       // 1536
#define IN_  (V_ + TS_)     // 1088

typedef unsigned long long ull;

// ---------------- packed fp32x2 helpers (Blackwell) ----------------
__device__ __forceinline__ ull ffma2(ull a, ull b, ull c) {
    ull d;
    asm("fma.rn.f32x2 %0, %1, %2, %3;" : "=l"(d) : "l"(a), "l"(b), "l"(c));
    return d;
}
__device__ __forceinline__ ull dup2(float a) {
    ull d; unsigned u = __float_as_uint(a);
    asm("mov.b64 %0, {%1, %2};" : "=l"(d) : "r"(u), "r"(u));
    return d;
}
__device__ __forceinline__ float2 u2f(ull a) {
    float2 f; unsigned lo, hi;
    asm("mov.b64 {%0, %1}, %2;" : "=r"(lo), "=r"(hi) : "l"(a));
    f.x = __uint_as_float(lo); f.y = __uint_as_float(hi);
    return f;
}
__device__ __forceinline__ float tanhfast(float x) {
    float y; asm("tanh.approx.f32 %0, %1;" : "=f"(y) : "f"(x)); return y;
}

// ---------------- device scratch ----------------
__device__ float g_xg[NTOK * G3];
__device__ float g_coefA[G3];
__device__ float g_coefC[G3];

// ---------------- kernel 0 ----------------
__global__ void coef_kernel(const float* __restrict__ W_time,
                            const float* __restrict__ b_time,
                            const float* __restrict__ W_ih,
                            const float* __restrict__ b_ih)
{
    int g = blockIdx.x * blockDim.x + threadIdx.x;
    if (g >= G3) return;
    const float* wrow = W_ih + (size_t)g * IN_ + V_;
    float a = 0.f, cc = 0.f;
#pragma unroll 8
    for (int j = 0; j < TS_; j++) {
        float wv = wrow[j];
        a  += W_time[j] * wv;
        cc += b_time[j] * wv;
    }
    g_coefA[g] = a;
    g_coefC[g] = cc + b_ih[g];
}

// ---------------- kernel 1: GEMM ----------------
#define BM 128
#define BN 128
#define BK 16
#define AST 132

__global__ __launch_bounds__(256, 2)
void gemm_kernel(const float* __restrict__ A,
                 const float* __restrict__ Bw,
                 const float* __restrict__ interval)
{
    __shared__ float As[BK][AST];
    __shared__ float Bs[BK][AST];

    int tid = threadIdx.x;
    int tx = tid & 15;
    int ty = tid >> 4;
    int rowBase = blockIdx.y * BM;
    int colBase = blockIdx.x * BN;

    int lr = tid >> 2;
    int kq = tid & 3;

    ull acc2[8][4];
#pragma unroll
    for (int i = 0; i < 8; i++)
#pragma unroll
        for (int j = 0; j < 4; j++) acc2[i][j] = 0ull;

    const float* Aptr = A  + (size_t)(rowBase + lr) * V_  + kq * 4;
    const float* Bptr = Bw + (size_t)(colBase + lr) * IN_ + kq * 4;

    for (int kt = 0; kt < V_; kt += BK) {
        float4 a0 = *(const float4*)(Aptr + kt);
        float4 a1 = *(const float4*)(Aptr + (size_t)64 * V_ + kt);
        float4 b0 = *(const float4*)(Bptr + kt);
        float4 b1 = *(const float4*)(Bptr + (size_t)64 * IN_ + kt);

        __syncthreads();
        As[kq*4+0][lr] = a0.x; As[kq*4+1][lr] = a0.y; As[kq*4+2][lr] = a0.z; As[kq*4+3][lr] = a0.w;
        As[kq*4+0][lr+64] = a1.x; As[kq*4+1][lr+64] = a1.y; As[kq*4+2][lr+64] = a1.z; As[kq*4+3][lr+64] = a1.w;
        Bs[kq*4+0][lr] = b0.x; Bs[kq*4+1][lr] = b0.y; Bs[kq*4+2][lr] = b0.z; Bs[kq*4+3][lr] = b0.w;
        Bs[kq*4+0][lr+64] = b1.x; Bs[kq*4+1][lr+64] = b1.y; Bs[kq*4+2][lr+64] = b1.z; Bs[kq*4+3][lr+64] = b1.w;
        __syncthreads();

#pragma unroll
        for (int kk = 0; kk < BK; kk++) {
            const float* ap = &As[kk][ty*8];
            float av[8];
            *(float4*)(av+0) = *(const float4*)(ap);
            *(float4*)(av+4) = *(const float4*)(ap + 4);
            const ull* bp = (const ull*)&Bs[kk][tx*8];
            ull bv0 = bp[0], bv1 = bp[1], bv2 = bp[2], bv3 = bp[3];
#pragma unroll
            for (int i = 0; i < 8; i++) {
                ull a2 = dup2(av[i]);
                acc2[i][0] = ffma2(a2, bv0, acc2[i][0]);
                acc2[i][1] = ffma2(a2, bv1, acc2[i][1]);
                acc2[i][2] = ffma2(a2, bv2, acc2[i][2]);
                acc2[i][3] = ffma2(a2, bv3, acc2[i][3]);
            }
        }
    }

    float ai[8], ca[8], cc[8];
#pragma unroll
    for (int i = 0; i < 8; i++) ai[i] = interval[rowBase + ty*8 + i];
#pragma unroll
    for (int j = 0; j < 8; j++) {
        ca[j] = g_coefA[colBase + tx*8 + j];
        cc[j] = g_coefC[colBase + tx*8 + j];
    }
#pragma unroll
    for (int i = 0; i < 8; i++) {
        size_t rbase = (size_t)(rowBase + ty*8 + i) * G3 + colBase + tx*8;
#pragma unroll
        for (int q = 0; q < 2; q++) {
            float2 v0 = u2f(acc2[i][2*q+0]);
            float2 v1 = u2f(acc2[i][2*q+1]);
            float4 o;
            o.x = v0.x + ai[i] * ca[4*q+0] + cc[4*q+0];
            o.y = v0.y + ai[i] * ca[4*q+1] + cc[4*q+1];
            o.z = v1.x + ai[i] * ca[4*q+2] + cc[4*q+2];
            o.w = v1.y + ai[i] * ca[4*q+3] + cc[4*q+3];
            *(float4*)&g_xg[rbase + 4*q] = o;
        }
    }
}

// ---------------- kernel 2: persistent cluster GRU scan (R3 + fixes) ----------------
// 16-CTA cluster, 512 threads. Warp w of CTA c owns units j0=32c+2w, j0+1.
// Rows r,z (4) in registers as f32x2; rows n (2) in 64KB smem (no spills).
// Sync: per dest, 2 mbarriers per parity (8 arrives each, by source-CTA parity).
// Publish: warp w ships stage[0..31] (all 32 CTA units) to CTA w's hb[p^1],
// then lane0 arrives (release.cluster) on CTA w's half-barrier.

#define WSM_BYTES   65536                         // 16w x 2r x 4qq x 32l x 16B
#define SMEM_MBARS  (WSM_BYTES)                   // 4 x 8B
#define SMEM_HB     (SMEM_MBARS + 32)             // 2 x 512 floats
#define SMEM_STAGE  (SMEM_HB + 4096)              // 32 floats
#define SMEM_BHH    (SMEM_STAGE + 128)            // 96 floats
#define SMEM_LENS   (SMEM_BHH + 384)              // 128 ints
#define SCAN_SMEM   (SMEM_LENS + 512)

__device__ __forceinline__ int hperm(int col) {
    return ((col >> 2) & 3) * 128 + ((col >> 4) << 2) + (col & 3);
}

__device__ __forceinline__ void waitParityCluster(uint32_t addr, int ph) {
    asm volatile(
        "{\n\t"
        ".reg .pred p;\n\t"
        "WLOOP_%=:\n\t"
        "mbarrier.try_wait.parity.acquire.cluster.shared::cta.b64 p, [%0], %1, 0x989680;\n\t"
        "@p bra WDONE_%=;\n\t"
        "bra WLOOP_%=;\n\t"
        "WDONE_%=:\n\t"
        "}"
        :: "r"(addr), "r"(ph) : "memory");
}

__global__ void __launch_bounds__(512, 1)
scan_kernel(const float* __restrict__ W_hh,
            const float* __restrict__ b_hh,
            const int*   __restrict__ lens,
            float*       __restrict__ out)
{
    extern __shared__ char smc[];
    ull*   wsm     = (ull*)smc;                     // n-gate weights
    float* hb      = (float*)(smc + SMEM_HB);       // [2][512] permuted
    float* stage   = (float*)(smc + SMEM_STAGE);
    float* bhh     = (float*)(smc + SMEM_BHH);
    int*   lens_sm = (int*)(smc + SMEM_LENS);
    uint32_t mb_s  = (uint32_t)__cvta_generic_to_shared(smc + SMEM_MBARS);

    int tid = threadIdx.x;
    int w = tid >> 5;
    int l = tid & 31;
    uint32_t c;
    asm("mov.u32 %0, %%cluster_ctarank;" : "=r"(c));

    hb[tid] = 0.f;
    hb[512 + tid] = 0.f;
    if (tid < 128) lens_sm[tid] = lens[tid];
    if (tid < 96) {
        int g = tid >> 5, u = tid & 31;
        bhh[tid] = b_hh[g * H_ + 32 * (int)c + u];
    }
    if (tid < 4) {
        asm volatile("mbarrier.init.shared.b64 [%0], 8;"
                     :: "r"(mb_s + 8u * tid) : "memory");
    }

    int j0 = 32 * (int)c + 2 * w;

    // rows r (0,1) and z (2,3) in registers
    ull W2[4][8];
#pragma unroll
    for (int r = 0; r < 4; r++) {
        int row = (r < 2) ? (j0 + r) : (H_ + j0 + r - 2);
        const ull* wp = (const ull*)(W_hh + (size_t)row * H_ + 16 * l);
#pragma unroll
        for (int k = 0; k < 8; k++) W2[r][k] = wp[k];
    }
    // rows n (4,5) into smem: wsm[(((w*2+r)*4+qq)*32 + l)*2 + j]
#pragma unroll
    for (int r = 0; r < 2; r++) {
        int row = 2 * H_ + j0 + r;
        const ull* wp = (const ull*)(W_hh + (size_t)row * H_ + 16 * l);
#pragma unroll
        for (int k = 0; k < 8; k++)
            wsm[(size_t)(((w * 2 + r) * 4 + (k >> 1)) * 32 + l) * 2 + (k & 1)] = wp[k];
    }
    __syncthreads();
    asm volatile("barrier.cluster.arrive.aligned;" ::: "memory");
    asm volatile("barrier.cluster.wait.aligned;"   ::: "memory");

    // remote addresses: warp w ships to CTA w
    uint32_t hb_u = (uint32_t)__cvta_generic_to_shared(hb);
    uint32_t ra_h0, ra_h1, ra_a0, ra_a1;
    {
        uint32_t la0 = hb_u + (uint32_t)(hperm(32 * (int)c + l) * 4);
        asm("mapa.shared::cluster.u32 %0, %1, %2;" : "=r"(ra_h0) : "r"(la0), "r"(w));
        ra_h1 = ra_h0 + 2048u;
        uint32_t lam0 = mb_s + 8u * (0u * 2u + (c & 1u));   // dest-buffer 0 half
        uint32_t lam1 = mb_s + 8u * (1u * 2u + (c & 1u));   // dest-buffer 1 half
        asm("mapa.shared::cluster.u32 %0, %1, %2;" : "=r"(ra_a0) : "r"(lam0), "r"(w));
        asm("mapa.shared::cluster.u32 %0, %1, %2;" : "=r"(ra_a1) : "r"(lam1), "r"(w));
    }

    float br = 0.f, bz = 0.f, bn = 0.f;
    if (l < 2) {
        int bidx = 2 * w + l;
        br = bhh[bidx]; bz = bhh[32 + bidx]; bn = bhh[64 + bidx];
    }

    int p = 0, ph0 = 0, ph1 = 0;
    bool pending = false;

    for (int b = 0; b < B_; b++) {
        int len = lens_sm[b];
        for (int t = 0; t < len; t++) {
            // xg loads issued BEFORE the sync wait (latency overlaps trywait)
            float xr = 0.f, xz = 0.f, xn = 0.f;
            if (l < 2) {
                const float* xp = g_xg + (size_t)((b << 6) + t) * G3 + (j0 + l);
                xr = __ldg(xp);
                xz = __ldg(xp + H_);
                xn = __ldg(xp + 2 * H_);
            }

            if (pending) {
                if (p == 0) {
                    waitParityCluster(mb_s,      ph0);
                    waitParityCluster(mb_s + 8,  ph0);
                    ph0 ^= 1;
                } else {
                    waitParityCluster(mb_s + 16, ph1);
                    waitParityCluster(mb_s + 24, ph1);
                    ph1 ^= 1;
                }
                pending = false;
            }

            // ---- matvec: rows 0-3 from regs, rows 4-5 from smem ----
            const float* hp = hb + p * 512;
            ull acc2[6] = {0ull, 0ull, 0ull, 0ull, 0ull, 0ull};
#pragma unroll
            for (int qq = 0; qq < 4; qq++) {
                const ull* hq = (const ull*)(hp + qq * 128 + l * 4);
                ull h01 = hq[0], h23 = hq[1];
#pragma unroll
                for (int r = 0; r < 4; r++) acc2[r] = ffma2(W2[r][2*qq+0], h01, acc2[r]);
#pragma unroll
                for (int r = 0; r < 4; r++) acc2[r] = ffma2(W2[r][2*qq+1], h23, acc2[r]);
                const ull* w4 = wsm + (size_t)(((w * 2 + 0) * 4 + qq) * 32 + l) * 2;
                const ull* w5 = wsm + (size_t)(((w * 2 + 1) * 4 + qq) * 32 + l) * 2;
                acc2[4] = ffma2(w4[0], h01, acc2[4]);
                acc2[4] = ffma2(w4[1], h23, acc2[4]);
                acc2[5] = ffma2(w5[0], h01, acc2[5]);
                acc2[5] = ffma2(w5[1], h23, acc2[5]);
            }
            float acc[6];
#pragma unroll
            for (int r = 0; r < 6; r++) { float2 f = u2f(acc2[r]); acc[r] = f.x + f.y; }

#pragma unroll
            for (int off = 16; off > 0; off >>= 1) {
#pragma unroll
                for (int r = 0; r < 6; r++)
                    acc[r] += __shfl_xor_sync(0xffffffffu, acc[r], off);
            }

            if (l < 2) {
                float hold = hp[hperm(j0 + l)];
                float rr = 0.5f * tanhfast(0.5f * (xr + acc[l]     + br)) + 0.5f;
                float zz = 0.5f * tanhfast(0.5f * (xz + acc[2 + l] + bz)) + 0.5f;
                float nn = tanhfast(xn + rr * (acc[4 + l] + bn));
                stage[2 * w + l] = fmaf(zz, hold - nn, nn);
            }
            __syncthreads();

            // ---- publish to CTA w's buffer p^1, then arrive on its half-barrier ----
            {
                float v = stage[l];
                uint32_t ra = p ? ra_h0 : ra_h1;
                asm volatile("st.shared::cluster.b32 [%0], %1;"
                             :: "r"(ra), "r"(__float_as_uint(v)) : "memory");
                __syncwarp();
                if (l == 0) {
                    uint32_t rm = p ? ra_a0 : ra_a1;
                    asm volatile("mbarrier.arrive.release.cluster.shared::cluster.b64 _, [%0];"
                                 :: "r"(rm) : "memory");
                }
            }
            p ^= 1;
            pending = true;
        }

        if (pending) {
            if (p == 0) {
                waitParityCluster(mb_s,      ph0);
                waitParityCluster(mb_s + 8,  ph0);
                ph0 ^= 1;
            } else {
                waitParityCluster(mb_s + 16, ph1);
                waitParityCluster(mb_s + 24, ph1);
                ph1 ^= 1;
            }
            pending = false;
        }
        if (tid < 32) {
            int j = 32 * (int)c + tid;
            out[b * H_ + j] = hb[p * 512 + hperm(j)];
        }
    }

    asm volatile("barrier.cluster.arrive.aligned;" ::: "memory");
    asm volatile("barrier.cluster.wait.aligned;"   ::: "memory");
}

// ---------------- launcher ----------------
extern "C" void kernel_launch(void* const* d_in, const int* in_sizes, int n_in,
                              void* d_out, int out_size)
{
    const float* visit_emb = (const float*)d_in[0];
    const float* intervals = (const float*)d_in[1];
    const float* W_time    = (const float*)d_in[2];
    const float* b_time    = (const float*)d_in[3];
    const float* W_ih      = (const float*)d_in[4];
    const float* W_hh      = (const float*)d_in[5];
    const float* b_ih      = (const float*)d_in[6];
    const float* b_hh      = (const float*)d_in[7];
    const int*   lens      = (const int*)d_in[8];
    float* out = (float*)d_out;

    coef_kernel<<<(G3 + 255) / 256, 256>>>(W_time, b_time, W_ih, b_ih);

    dim3 ggrid(G3 / BN, NTOK / BM);   // (12, 64)
    gemm_kernel<<<ggrid, 256>>>(visit_emb, W_ih, intervals);

    cudaFuncSetAttribute(scan_kernel, cudaFuncAttributeNonPortableClusterSizeAllowed, 1);
    cudaFuncSetAttribute(scan_kernel, cudaFuncAttributeMaxDynamicSharedMemorySize, SCAN_SMEM);

    cudaLaunchConfig_t cfg = {};
    cfg.gridDim  = dim3(16, 1, 1);
    cfg.blockDim = dim3(512, 1, 1);
    cfg.dynamicSmemBytes = SCAN_SMEM;
    cfg.stream = 0;
    cudaLaunchAttribute attrs[1];
    attrs[0].id = cudaLaunchAttributeClusterDimension;
    attrs[0].val.clusterDim.x = 16;
    attrs[0].val.clusterDim.y = 1;
    attrs[0].val.clusterDim.z = 1;
    cfg.attrs = attrs;
    cfg.numAttrs = 1;

    cudaLaunchKernelEx(&cfg, scan_kernel, W_hh, b_hh, lens, out);
}

// round 8
// speedup vs baseline: 3.0438x; 1.0276x over previous
#include <cuda_runtime.h>
#include <cstdint>

#define B_   128
#define T_   64
#define V_   1024
#define TS_  64
#define H_   512
#define NTOK (B_ * T_)      // 8192
#define G3   (3 * H_)       // 1536
#define IN_  (V_ + TS_)     // 1088

typedef unsigned long long ull;

// ---------------- packed fp32x2 helpers (Blackwell) ----------------
__device__ __forceinline__ ull ffma2(ull a, ull b, ull c) {
    ull d;
    asm("fma.rn.f32x2 %0, %1, %2, %3;" : "=l"(d) : "l"(a), "l"(b), "l"(c));
    return d;
}
__device__ __forceinline__ ull dup2(float a) {
    ull d; unsigned u = __float_as_uint(a);
    asm("mov.b64 %0, {%1, %2};" : "=l"(d) : "r"(u), "r"(u));
    return d;
}
__device__ __forceinline__ float2 u2f(ull a) {
    float2 f; unsigned lo, hi;
    asm("mov.b64 {%0, %1}, %2;" : "=r"(lo), "=r"(hi) : "l"(a));
    f.x = __uint_as_float(lo); f.y = __uint_as_float(hi);
    return f;
}
__device__ __forceinline__ float tanhfast(float x) {
    float y; asm("tanh.approx.f32 %0, %1;" : "=f"(y) : "f"(x)); return y;
}

// ---------------- device scratch ----------------
__device__ float g_xg[NTOK * G3];

// ---------------- kernel 1: fused coef + GEMM ----------------
// xg = visit_emb @ W_ih[:, :V]^T + interval*A + C, where A/C fold the
// time-embedding (Linear(1,TS) -> W_ih[:, V:]) into per-gate scalars,
// computed per-block for its 128 columns.
#define BM 128
#define BN 128
#define BK 16
#define AST 132

__global__ __launch_bounds__(256, 2)
void gemm_kernel(const float* __restrict__ A,
                 const float* __restrict__ Bw,
                 const float* __restrict__ interval,
                 const float* __restrict__ W_time,
                 const float* __restrict__ b_time,
                 const float* __restrict__ b_ih)
{
    __shared__ float As[BK][AST];
    __shared__ float Bs[BK][AST];
    __shared__ float caS[BN], ccS[BN];

    int tid = threadIdx.x;
    int tx = tid & 15;
    int ty = tid >> 4;
    int rowBase = blockIdx.y * BM;
    int colBase = blockIdx.x * BN;

    // per-block coefficient fold (columns colBase..colBase+127)
    if (tid < BN) {
        int g = colBase + tid;
        const float* wrow = Bw + (size_t)g * IN_ + V_;
        float a = 0.f, cc = 0.f;
#pragma unroll 8
        for (int j = 0; j < TS_; j++) {
            float wv = wrow[j];
            a  += W_time[j] * wv;
            cc += b_time[j] * wv;
        }
        caS[tid] = a;
        ccS[tid] = cc + b_ih[g];
    }

    int lr = tid >> 2;
    int kq = tid & 3;

    ull acc2[8][4];
#pragma unroll
    for (int i = 0; i < 8; i++)
#pragma unroll
        for (int j = 0; j < 4; j++) acc2[i][j] = 0ull;

    const float* Aptr = A  + (size_t)(rowBase + lr) * V_  + kq * 4;
    const float* Bptr = Bw + (size_t)(colBase + lr) * IN_ + kq * 4;

    for (int kt = 0; kt < V_; kt += BK) {
        float4 a0 = *(const float4*)(Aptr + kt);
        float4 a1 = *(const float4*)(Aptr + (size_t)64 * V_ + kt);
        float4 b0 = *(const float4*)(Bptr + kt);
        float4 b1 = *(const float4*)(Bptr + (size_t)64 * IN_ + kt);

        __syncthreads();
        As[kq*4+0][lr] = a0.x; As[kq*4+1][lr] = a0.y; As[kq*4+2][lr] = a0.z; As[kq*4+3][lr] = a0.w;
        As[kq*4+0][lr+64] = a1.x; As[kq*4+1][lr+64] = a1.y; As[kq*4+2][lr+64] = a1.z; As[kq*4+3][lr+64] = a1.w;
        Bs[kq*4+0][lr] = b0.x; Bs[kq*4+1][lr] = b0.y; Bs[kq*4+2][lr] = b0.z; Bs[kq*4+3][lr] = b0.w;
        Bs[kq*4+0][lr+64] = b1.x; Bs[kq*4+1][lr+64] = b1.y; Bs[kq*4+2][lr+64] = b1.z; Bs[kq*4+3][lr+64] = b1.w;
        __syncthreads();

#pragma unroll
        for (int kk = 0; kk < BK; kk++) {
            const float* ap = &As[kk][ty*8];
            float av[8];
            *(float4*)(av+0) = *(const float4*)(ap);
            *(float4*)(av+4) = *(const float4*)(ap + 4);
            const ull* bp = (const ull*)&Bs[kk][tx*8];
            ull bv0 = bp[0], bv1 = bp[1], bv2 = bp[2], bv3 = bp[3];
#pragma unroll
            for (int i = 0; i < 8; i++) {
                ull a2 = dup2(av[i]);
                acc2[i][0] = ffma2(a2, bv0, acc2[i][0]);
                acc2[i][1] = ffma2(a2, bv1, acc2[i][1]);
                acc2[i][2] = ffma2(a2, bv2, acc2[i][2]);
                acc2[i][3] = ffma2(a2, bv3, acc2[i][3]);
            }
        }
    }

    float ai[8], ca[8], cc[8];
#pragma unroll
    for (int i = 0; i < 8; i++) ai[i] = interval[rowBase + ty*8 + i];
#pragma unroll
    for (int j = 0; j < 8; j++) {
        ca[j] = caS[tx*8 + j];
        cc[j] = ccS[tx*8 + j];
    }
#pragma unroll
    for (int i = 0; i < 8; i++) {
        size_t rbase = (size_t)(rowBase + ty*8 + i) * G3 + colBase + tx*8;
#pragma unroll
        for (int q = 0; q < 2; q++) {
            float2 v0 = u2f(acc2[i][2*q+0]);
            float2 v1 = u2f(acc2[i][2*q+1]);
            float4 o;
            o.x = v0.x + ai[i] * ca[4*q+0] + cc[4*q+0];
            o.y = v0.y + ai[i] * ca[4*q+1] + cc[4*q+1];
            o.z = v1.x + ai[i] * ca[4*q+2] + cc[4*q+2];
            o.w = v1.y + ai[i] * ca[4*q+3] + cc[4*q+3];
            *(float4*)&g_xg[rbase + 4*q] = o;
        }
    }
}

// ---------------- kernel 2: persistent cluster GRU scan ----------------
// 16-CTA cluster, 512 threads. Warp w of CTA c owns units j0=32c+2w, j0+1.
// Rows r,z (4) in registers as f32x2; rows n (2) in 64KB smem (no spills).
// Split-butterfly warp reduce (21 SHFLs instead of 30). Sync: per dest, 2
// mbarriers per parity (8 arrives each by src-CTA parity). Publish: warp w
// ships stage[0..31] to CTA w's hb[p^1], lane0 arrives release.cluster.

#define WSM_BYTES   65536
#define SMEM_MBARS  (WSM_BYTES)
#define SMEM_HB     (SMEM_MBARS + 32)
#define SMEM_STAGE  (SMEM_HB + 4096)
#define SMEM_BHH    (SMEM_STAGE + 128)
#define SMEM_LENS   (SMEM_BHH + 384)
#define SCAN_SMEM   (SMEM_LENS + 512)

__device__ __forceinline__ int hperm(int col) {
    return ((col >> 2) & 3) * 128 + ((col >> 4) << 2) + (col & 3);
}

__device__ __forceinline__ void waitParityCluster(uint32_t addr, int ph) {
    asm volatile(
        "{\n\t"
        ".reg .pred p;\n\t"
        "WLOOP_%=:\n\t"
        "mbarrier.try_wait.parity.acquire.cluster.shared::cta.b64 p, [%0], %1, 0x989680;\n\t"
        "@p bra WDONE_%=;\n\t"
        "bra WLOOP_%=;\n\t"
        "WDONE_%=:\n\t"
        "}"
        :: "r"(addr), "r"(ph) : "memory");
}

__global__ void __launch_bounds__(512, 1)
scan_kernel(const float* __restrict__ W_hh,
            const float* __restrict__ b_hh,
            const int*   __restrict__ lens,
            float*       __restrict__ out)
{
    extern __shared__ char smc[];
    ull*   wsm     = (ull*)smc;
    float* hb      = (float*)(smc + SMEM_HB);
    float* stage   = (float*)(smc + SMEM_STAGE);
    float* bhh     = (float*)(smc + SMEM_BHH);
    int*   lens_sm = (int*)(smc + SMEM_LENS);
    uint32_t mb_s  = (uint32_t)__cvta_generic_to_shared(smc + SMEM_MBARS);

    int tid = threadIdx.x;
    int w = tid >> 5;
    int l = tid & 31;
    uint32_t c;
    asm("mov.u32 %0, %%cluster_ctarank;" : "=r"(c));

    hb[tid] = 0.f;
    hb[512 + tid] = 0.f;
    if (tid < 128) lens_sm[tid] = lens[tid];
    if (tid < 96) {
        int g = tid >> 5, u = tid & 31;
        bhh[tid] = b_hh[g * H_ + 32 * (int)c + u];
    }
    if (tid < 4) {
        asm volatile("mbarrier.init.shared.b64 [%0], 8;"
                     :: "r"(mb_s + 8u * tid) : "memory");
    }

    int j0 = 32 * (int)c + 2 * w;

    ull W2[4][8];
#pragma unroll
    for (int r = 0; r < 4; r++) {
        int row = (r < 2) ? (j0 + r) : (H_ + j0 + r - 2);
        const ull* wp = (const ull*)(W_hh + (size_t)row * H_ + 16 * l);
#pragma unroll
        for (int k = 0; k < 8; k++) W2[r][k] = wp[k];
    }
#pragma unroll
    for (int r = 0; r < 2; r++) {
        int row = 2 * H_ + j0 + r;
        const ull* wp = (const ull*)(W_hh + (size_t)row * H_ + 16 * l);
#pragma unroll
        for (int k = 0; k < 8; k++)
            wsm[(size_t)(((w * 2 + r) * 4 + (k >> 1)) * 32 + l) * 2 + (k & 1)] = wp[k];
    }
    __syncthreads();
    asm volatile("barrier.cluster.arrive.aligned;" ::: "memory");
    asm volatile("barrier.cluster.wait.aligned;"   ::: "memory");

    uint32_t hb_u = (uint32_t)__cvta_generic_to_shared(hb);
    uint32_t ra_h0, ra_h1, ra_a0, ra_a1;
    {
        uint32_t la0 = hb_u + (uint32_t)(hperm(32 * (int)c + l) * 4);
        asm("mapa.shared::cluster.u32 %0, %1, %2;" : "=r"(ra_h0) : "r"(la0), "r"(w));
        ra_h1 = ra_h0 + 2048u;
        uint32_t lam0 = mb_s + 8u * (0u * 2u + (c & 1u));
        uint32_t lam1 = mb_s + 8u * (1u * 2u + (c & 1u));
        asm("mapa.shared::cluster.u32 %0, %1, %2;" : "=r"(ra_a0) : "r"(lam0), "r"(w));
        asm("mapa.shared::cluster.u32 %0, %1, %2;" : "=r"(ra_a1) : "r"(lam1), "r"(w));
    }

    float br = 0.f, bz = 0.f, bn = 0.f;
    if (l < 2) {
        int bidx = 2 * w + l;
        br = bhh[bidx]; bz = bhh[32 + bidx]; bn = bhh[64 + bidx];
    }

    int p = 0, ph0 = 0, ph1 = 0;
    bool pending = false;

    for (int b = 0; b < B_; b++) {
        int len = lens_sm[b];
        for (int t = 0; t < len; t++) {
            // xg loads issued BEFORE the sync wait (latency overlaps trywait)
            float xr = 0.f, xz = 0.f, xn = 0.f;
            if (l < 2) {
                const float* xp = g_xg + (size_t)((b << 6) + t) * G3 + (j0 + l);
                xr = __ldg(xp);
                xz = __ldg(xp + H_);
                xn = __ldg(xp + 2 * H_);
            }

            if (pending) {
                if (p == 0) {
                    waitParityCluster(mb_s,      ph0);
                    waitParityCluster(mb_s + 8,  ph0);
                    ph0 ^= 1;
                } else {
                    waitParityCluster(mb_s + 16, ph1);
                    waitParityCluster(mb_s + 24, ph1);
                    ph1 ^= 1;
                }
                pending = false;
            }

            const float* hp = hb + p * 512;
            float hold = 0.f;
            if (l < 2) hold = hp[hperm(j0 + l)];

            ull acc2[6] = {0ull, 0ull, 0ull, 0ull, 0ull, 0ull};
#pragma unroll
            for (int qq = 0; qq < 4; qq++) {
                const ull* hq = (const ull*)(hp + qq * 128 + l * 4);
                ull h01 = hq[0], h23 = hq[1];
#pragma unroll
                for (int r = 0; r < 4; r++) acc2[r] = ffma2(W2[r][2*qq+0], h01, acc2[r]);
#pragma unroll
                for (int r = 0; r < 4; r++) acc2[r] = ffma2(W2[r][2*qq+1], h23, acc2[r]);
                const ull* w4 = wsm + (size_t)(((w * 2 + 0) * 4 + qq) * 32 + l) * 2;
                const ull* w5 = wsm + (size_t)(((w * 2 + 1) * 4 + qq) * 32 + l) * 2;
                acc2[4] = ffma2(w4[0], h01, acc2[4]);
                acc2[4] = ffma2(w4[1], h23, acc2[4]);
                acc2[5] = ffma2(w5[0], h01, acc2[5]);
                acc2[5] = ffma2(w5[1], h23, acc2[5]);
            }
            float acc[6];
#pragma unroll
            for (int r = 0; r < 6; r++) { float2 f = u2f(acc2[r]); acc[r] = f.x + f.y; }

            // ---- split-butterfly reduce: 6 + 12 + 3 SHFLs ----
            // round 1: full xor-16 on all 6 accs (both halves stay valid)
#pragma unroll
            for (int r = 0; r < 6; r++)
                acc[r] += __shfl_xor_sync(0xffffffffu, acc[r], 16);
            // low half (l<16) continues accs {0,1,2}; high half accs {3,4,5}
            bool hihalf = (l >= 16);
            float s0 = hihalf ? acc[3] : acc[0];
            float s1 = hihalf ? acc[4] : acc[1];
            float s2 = hihalf ? acc[5] : acc[2];
#pragma unroll
            for (int off = 8; off > 0; off >>= 1) {
                s0 += __shfl_xor_sync(0xffffffffu, s0, off);
                s1 += __shfl_xor_sync(0xffffffffu, s1, off);
                s2 += __shfl_xor_sync(0xffffffffu, s2, off);
            }
            // cross-half gather: lanes 16+ hold accs 3,4,5 in s0,s1,s2
            float t0 = __shfl_sync(0xffffffffu, s0, 16);   // acc3
            float t1 = __shfl_sync(0xffffffffu, s1, 16);   // acc4
            float t2 = __shfl_sync(0xffffffffu, s2, 16);   // acc5

            if (l < 2) {
                float a_r = l ? s1 : s0;   // acc[l]
                float a_z = l ? t0 : s2;   // acc[2+l]
                float a_n = l ? t2 : t1;   // acc[4+l]
                float rr = 0.5f * tanhfast(0.5f * (xr + a_r + br)) + 0.5f;
                float zz = 0.5f * tanhfast(0.5f * (xz + a_z + bz)) + 0.5f;
                float nn = tanhfast(xn + rr * (a_n + bn));
                stage[2 * w + l] = fmaf(zz, hold - nn, nn);
            }
            __syncthreads();

            {
                float v = stage[l];
                uint32_t ra = p ? ra_h0 : ra_h1;
                asm volatile("st.shared::cluster.b32 [%0], %1;"
                             :: "r"(ra), "r"(__float_as_uint(v)) : "memory");
                __syncwarp();
                if (l == 0) {
                    uint32_t rm = p ? ra_a0 : ra_a1;
                    asm volatile("mbarrier.arrive.release.cluster.shared::cluster.b64 _, [%0];"
                                 :: "r"(rm) : "memory");
                }
            }
            p ^= 1;
            pending = true;
        }

        if (pending) {
            if (p == 0) {
                waitParityCluster(mb_s,      ph0);
                waitParityCluster(mb_s + 8,  ph0);
                ph0 ^= 1;
            } else {
                waitParityCluster(mb_s + 16, ph1);
                waitParityCluster(mb_s + 24, ph1);
                ph1 ^= 1;
            }
            pending = false;
        }
        if (tid < 32) {
            int j = 32 * (int)c + tid;
            out[b * H_ + j] = hb[p * 512 + hperm(j)];
        }
    }

    asm volatile("barrier.cluster.arrive.aligned;" ::: "memory");
    asm volatile("barrier.cluster.wait.aligned;"   ::: "memory");
}

// ---------------- launcher ----------------
extern "C" void kernel_launch(void* const* d_in, const int* in_sizes, int n_in,
                              void* d_out, int out_size)
{
    const float* visit_emb = (const float*)d_in[0];
    const float* intervals = (const float*)d_in[1];
    const float* W_time    = (const float*)d_in[2];
    const float* b_time    = (const float*)d_in[3];
    const float* W_ih      = (const float*)d_in[4];
    const float* W_hh      = (const float*)d_in[5];
    const float* b_ih      = (const float*)d_in[6];
    const float* b_hh      = (const float*)d_in[7];
    const int*   lens      = (const int*)d_in[8];
    float* out = (float*)d_out;

    dim3 ggrid(G3 / BN, NTOK / BM);   // (12, 64)
    gemm_kernel<<<ggrid, 256>>>(visit_emb, W_ih, intervals, W_time, b_time, b_ih);

    cudaFuncSetAttribute(scan_kernel, cudaFuncAttributeNonPortableClusterSizeAllowed, 1);
    cudaFuncSetAttribute(scan_kernel, cudaFuncAttributeMaxDynamicSharedMemorySize, SCAN_SMEM);

    cudaLaunchConfig_t cfg = {};
    cfg.gridDim  = dim3(16, 1, 1);
    cfg.blockDim = dim3(512, 1, 1);
    cfg.dynamicSmemBytes = SCAN_SMEM;
    cfg.stream = 0;
    cudaLaunchAttribute attrs[1];
    attrs[0].id = cudaLaunchAttributeClusterDimension;
    attrs[0].val.clusterDim.x = 16;
    attrs[0].val.clusterDim.y = 1;
    attrs[0].val.clusterDim.z = 1;
    cfg.attrs = attrs;
    cfg.numAttrs = 1;

    cudaLaunchKernelEx(&cfg, scan_kernel, W_hh, b_hh, lens, out);
}

// round 9
// speedup vs baseline: 3.3626x; 1.1047x over previous
#include <cuda_runtime.h>
#include <cstdint>

#define B_   128
#define T_   64
#define V_   1024
#define TS_  64
#define H_   512
#define NTOK (B_ * T_)      // 8192
#define G3   (3 * H_)       // 1536
#define IN_  (V_ + TS_)     // 1088

typedef unsigned long long ull;

// ---------------- packed fp32x2 helpers (Blackwell) ----------------
__device__ __forceinline__ ull ffma2(ull a, ull b, ull c) {
    ull d;
    asm("fma.rn.f32x2 %0, %1, %2, %3;" : "=l"(d) : "l"(a), "l"(b), "l"(c));
    return d;
}
__device__ __forceinline__ ull dup2(float a) {
    ull d; unsigned u = __float_as_uint(a);
    asm("mov.b64 %0, {%1, %2};" : "=l"(d) : "r"(u), "r"(u));
    return d;
}
__device__ __forceinline__ float2 u2f(ull a) {
    float2 f; unsigned lo, hi;
    asm("mov.b64 {%0, %1}, %2;" : "=r"(lo), "=r"(hi) : "l"(a));
    f.x = __uint_as_float(lo); f.y = __uint_as_float(hi);
    return f;
}
__device__ __forceinline__ float tanhfast(float x) {
    float y; asm("tanh.approx.f32 %0, %1;" : "=f"(y) : "f"(x)); return y;
}

// ---------------- device scratch ----------------
__device__ float    g_xg[NTOK * G3];
__device__ unsigned g_ready[64];          // per 128-token row-tile: #col-tiles done

// ---------------- layout constants ----------------
#define SCAN_CTAS   16
#define GEMM_BLOCKS 768                   // 64 row-tiles x 12 col-tiles
#define GRID_X      (SCAN_CTAS + GEMM_BLOCKS)

#define BM 128
#define BN 128
#define BK 16
#define AST 132

// scan smem layout (dynamic)
#define WSM_BYTES   65536
#define SMEM_MBARS  (WSM_BYTES)
#define SMEM_HB     (SMEM_MBARS + 32)
#define SMEM_STAGE  (SMEM_HB + 4096)
#define SMEM_BHH    (SMEM_STAGE + 128)
#define SMEM_LENS   (SMEM_BHH + 384)
#define SCAN_SMEM   (SMEM_LENS + 512)

__device__ __forceinline__ int hperm(int col) {
    return ((col >> 2) & 3) * 128 + ((col >> 4) << 2) + (col & 3);
}

__device__ __forceinline__ void waitParityCluster(uint32_t addr, int ph) {
    asm volatile(
        "{\n\t"
        ".reg .pred p;\n\t"
        "WLOOP_%=:\n\t"
        "mbarrier.try_wait.parity.acquire.cluster.shared::cta.b64 p, [%0], %1, 0x989680;\n\t"
        "@p bra WDONE_%=;\n\t"
        "bra WLOOP_%=;\n\t"
        "WDONE_%=:\n\t"
        "}"
        :: "r"(addr), "r"(ph) : "memory");
}

// ================= GEMM body (blocks 16..783, 512 threads) =================
__device__ void gemm_body(const float* __restrict__ A,
                          const float* __restrict__ Bw,
                          const float* __restrict__ interval,
                          const float* __restrict__ W_time,
                          const float* __restrict__ b_time,
                          const float* __restrict__ b_ih,
                          char* smc)
{
    float (*As)[AST] = (float (*)[AST])smc;
    float (*Bs)[AST] = (float (*)[AST])(smc + BK * AST * 4);
    float* caS = (float*)(smc + 2 * BK * AST * 4);
    float* ccS = caS + BN;

    int tid = threadIdx.x;
    int gemmIdx = blockIdx.x - SCAN_CTAS;
    int rowTile = gemmIdx / 12;
    int colTile = gemmIdx - rowTile * 12;
    int rowBase = rowTile * BM;
    int colBase = colTile * BN;

    // fold time-embedding into per-column coefficients
    if (tid < BN) {
        int g = colBase + tid;
        const float* wrow = Bw + (size_t)g * IN_ + V_;
        float a = 0.f, cc = 0.f;
#pragma unroll 8
        for (int j = 0; j < TS_; j++) {
            float wv = wrow[j];
            a  += W_time[j] * wv;
            cc += b_time[j] * wv;
        }
        caS[tid] = a;
        ccS[tid] = cc + b_ih[g];
    }

    int tx = tid & 15;          // 8 cols each
    int ty = tid >> 4;          // 4 rows each (0..31)
    int lr = tid >> 2;          // 0..127
    int kq = tid & 3;

    ull acc2[4][4];
#pragma unroll
    for (int i = 0; i < 4; i++)
#pragma unroll
        for (int j = 0; j < 4; j++) acc2[i][j] = 0ull;

    const float* Aptr = A  + (size_t)(rowBase + lr) * V_  + kq * 4;
    const float* Bptr = Bw + (size_t)(colBase + lr) * IN_ + kq * 4;

    for (int kt = 0; kt < V_; kt += BK) {
        float4 a0 = *(const float4*)(Aptr + kt);
        float4 b0 = *(const float4*)(Bptr + kt);

        __syncthreads();
        As[kq*4+0][lr] = a0.x; As[kq*4+1][lr] = a0.y; As[kq*4+2][lr] = a0.z; As[kq*4+3][lr] = a0.w;
        Bs[kq*4+0][lr] = b0.x; Bs[kq*4+1][lr] = b0.y; Bs[kq*4+2][lr] = b0.z; Bs[kq*4+3][lr] = b0.w;
        __syncthreads();

#pragma unroll
        for (int kk = 0; kk < BK; kk++) {
            float av[4];
            *(float4*)av = *(const float4*)&As[kk][ty*4];
            const ull* bp = (const ull*)&Bs[kk][tx*8];
            ull bv0 = bp[0], bv1 = bp[1], bv2 = bp[2], bv3 = bp[3];
#pragma unroll
            for (int i = 0; i < 4; i++) {
                ull a2 = dup2(av[i]);
                acc2[i][0] = ffma2(a2, bv0, acc2[i][0]);
                acc2[i][1] = ffma2(a2, bv1, acc2[i][1]);
                acc2[i][2] = ffma2(a2, bv2, acc2[i][2]);
                acc2[i][3] = ffma2(a2, bv3, acc2[i][3]);
            }
        }
    }

    float ai[4], ca[8], cc[8];
#pragma unroll
    for (int i = 0; i < 4; i++) ai[i] = interval[rowBase + ty*4 + i];
#pragma unroll
    for (int j = 0; j < 8; j++) {
        ca[j] = caS[tx*8 + j];
        cc[j] = ccS[tx*8 + j];
    }
#pragma unroll
    for (int i = 0; i < 4; i++) {
        size_t rbase = (size_t)(rowBase + ty*4 + i) * G3 + colBase + tx*8;
#pragma unroll
        for (int q = 0; q < 2; q++) {
            float2 v0 = u2f(acc2[i][2*q+0]);
            float2 v1 = u2f(acc2[i][2*q+1]);
            float4 o;
            o.x = v0.x + ai[i] * ca[4*q+0] + cc[4*q+0];
            o.y = v0.y + ai[i] * ca[4*q+1] + cc[4*q+1];
            o.z = v1.x + ai[i] * ca[4*q+2] + cc[4*q+2];
            o.w = v1.y + ai[i] * ca[4*q+3] + cc[4*q+3];
            *(float4*)&g_xg[rbase + 4*q] = o;
        }
    }

    // publish readiness of this col-tile for the row-tile
    __syncthreads();
    if (tid == 0) {
        __threadfence();
        atomicAdd(&g_ready[rowTile], 1u);
    }
}

// ================= scan body (blocks 0..15, one 16-CTA cluster) =================
__device__ void scan_body(const float* __restrict__ W_hh,
                          const float* __restrict__ b_hh,
                          const int*   __restrict__ lens,
                          float*       __restrict__ out,
                          char* smc)
{
    ull*   wsm     = (ull*)smc;
    float* hb      = (float*)(smc + SMEM_HB);
    float* stage   = (float*)(smc + SMEM_STAGE);
    float* bhh     = (float*)(smc + SMEM_BHH);
    int*   lens_sm = (int*)(smc + SMEM_LENS);
    uint32_t mb_s  = (uint32_t)__cvta_generic_to_shared(smc + SMEM_MBARS);

    int tid = threadIdx.x;
    int w = tid >> 5;
    int l = tid & 31;
    uint32_t c;
    asm("mov.u32 %0, %%cluster_ctarank;" : "=r"(c));

    hb[tid] = 0.f;
    hb[512 + tid] = 0.f;
    if (tid < 128) lens_sm[tid] = lens[tid];
    if (tid < 96) {
        int g = tid >> 5, u = tid & 31;
        bhh[tid] = b_hh[g * H_ + 32 * (int)c + u];
    }
    if (tid < 4) {
        asm volatile("mbarrier.init.shared.b64 [%0], 8;"
                     :: "r"(mb_s + 8u * tid) : "memory");
    }

    int j0 = 32 * (int)c + 2 * w;

    ull W2[4][8];
#pragma unroll
    for (int r = 0; r < 4; r++) {
        int row = (r < 2) ? (j0 + r) : (H_ + j0 + r - 2);
        const ull* wp = (const ull*)(W_hh + (size_t)row * H_ + 16 * l);
#pragma unroll
        for (int k = 0; k < 8; k++) W2[r][k] = wp[k];
    }
#pragma unroll
    for (int r = 0; r < 2; r++) {
        int row = 2 * H_ + j0 + r;
        const ull* wp = (const ull*)(W_hh + (size_t)row * H_ + 16 * l);
#pragma unroll
        for (int k = 0; k < 8; k++)
            wsm[(size_t)(((w * 2 + r) * 4 + (k >> 1)) * 32 + l) * 2 + (k & 1)] = wp[k];
    }
    __syncthreads();
    asm volatile("barrier.cluster.arrive.aligned;" ::: "memory");
    asm volatile("barrier.cluster.wait.aligned;"   ::: "memory");

    uint32_t hb_u = (uint32_t)__cvta_generic_to_shared(hb);
    // coalesced publish: lane g<8 ships stage[4g..4g+3] (units 32c+4g..+3) to
    // CTA w as ONE st.shared::cluster.v4 at the hperm-contiguous slot group.
    uint32_t ra_v = 0;
    if (l < 8) {
        int slotbase = (l & 3) * 128 + (2 * (int)c + (l >> 2)) * 4;
        uint32_t la = hb_u + (uint32_t)(slotbase * 4);
        asm("mapa.shared::cluster.u32 %0, %1, %2;" : "=r"(ra_v) : "r"(la), "r"(w));
    }
    uint32_t ra_a0, ra_a1;
    {
        uint32_t lam0 = mb_s + 8u * (0u * 2u + (c & 1u));
        uint32_t lam1 = mb_s + 8u * (1u * 2u + (c & 1u));
        asm("mapa.shared::cluster.u32 %0, %1, %2;" : "=r"(ra_a0) : "r"(lam0), "r"(w));
        asm("mapa.shared::cluster.u32 %0, %1, %2;" : "=r"(ra_a1) : "r"(lam1), "r"(w));
    }

    float br = 0.f, bz = 0.f, bn = 0.f;
    if (l < 2) {
        int bidx = 2 * w + l;
        br = bhh[bidx]; bz = bhh[32 + bidx]; bn = bhh[64 + bidx];
    }

    int p = 0, ph0 = 0, ph1 = 0;
    bool pending = false;
    int cur_tile = -1;

    for (int b = 0; b < B_; b++) {
        int len = lens_sm[b];
        for (int t = 0; t < len; t++) {
            int n = (b << 6) + t;

            // wait until this token's GEMM row-tile is complete (12 col-tiles)
            if ((n >> 7) != cur_tile) {
                cur_tile = n >> 7;
                unsigned rdy;
                do {
                    asm volatile("ld.acquire.gpu.global.u32 %0, [%1];"
                                 : "=r"(rdy) : "l"(g_ready + cur_tile) : "memory");
                } while (rdy < 12u);
            }

            // xg loads issued BEFORE the sync wait (latency overlaps trywait)
            float xr = 0.f, xz = 0.f, xn = 0.f;
            if (l < 2) {
                const float* xp = g_xg + (size_t)n * G3 + (j0 + l);
                xr = __ldg(xp);
                xz = __ldg(xp + H_);
                xn = __ldg(xp + 2 * H_);
            }

            if (pending) {
                if (p == 0) {
                    waitParityCluster(mb_s,      ph0);
                    waitParityCluster(mb_s + 8,  ph0);
                    ph0 ^= 1;
                } else {
                    waitParityCluster(mb_s + 16, ph1);
                    waitParityCluster(mb_s + 24, ph1);
                    ph1 ^= 1;
                }
                pending = false;
            }

            const float* hp = hb + p * 512;
            float hold = 0.f;
            if (l < 2) hold = hp[hperm(j0 + l)];

            ull acc2[6] = {0ull, 0ull, 0ull, 0ull, 0ull, 0ull};
#pragma unroll
            for (int qq = 0; qq < 4; qq++) {
                const ull* hq = (const ull*)(hp + qq * 128 + l * 4);
                ull h01 = hq[0], h23 = hq[1];
#pragma unroll
                for (int r = 0; r < 4; r++) acc2[r] = ffma2(W2[r][2*qq+0], h01, acc2[r]);
#pragma unroll
                for (int r = 0; r < 4; r++) acc2[r] = ffma2(W2[r][2*qq+1], h23, acc2[r]);
                const ull* w4 = wsm + (size_t)(((w * 2 + 0) * 4 + qq) * 32 + l) * 2;
                const ull* w5 = wsm + (size_t)(((w * 2 + 1) * 4 + qq) * 32 + l) * 2;
                acc2[4] = ffma2(w4[0], h01, acc2[4]);
                acc2[4] = ffma2(w4[1], h23, acc2[4]);
                acc2[5] = ffma2(w5[0], h01, acc2[5]);
                acc2[5] = ffma2(w5[1], h23, acc2[5]);
            }
            float acc[6];
#pragma unroll
            for (int r = 0; r < 6; r++) { float2 f = u2f(acc2[r]); acc[r] = f.x + f.y; }

            // split-butterfly reduce: 6 + 12 + 3 SHFLs
#pragma unroll
            for (int r = 0; r < 6; r++)
                acc[r] += __shfl_xor_sync(0xffffffffu, acc[r], 16);
            bool hihalf = (l >= 16);
            float s0 = hihalf ? acc[3] : acc[0];
            float s1 = hihalf ? acc[4] : acc[1];
            float s2 = hihalf ? acc[5] : acc[2];
#pragma unroll
            for (int off = 8; off > 0; off >>= 1) {
                s0 += __shfl_xor_sync(0xffffffffu, s0, off);
                s1 += __shfl_xor_sync(0xffffffffu, s1, off);
                s2 += __shfl_xor_sync(0xffffffffu, s2, off);
            }
            float t0 = __shfl_sync(0xffffffffu, s0, 16);   // acc3
            float t1 = __shfl_sync(0xffffffffu, s1, 16);   // acc4
            float t2 = __shfl_sync(0xffffffffu, s2, 16);   // acc5

            if (l < 2) {
                float a_r = l ? s1 : s0;
                float a_z = l ? t0 : s2;
                float a_n = l ? t2 : t1;
                float rr = 0.5f * tanhfast(0.5f * (xr + a_r + br)) + 0.5f;
                float zz = 0.5f * tanhfast(0.5f * (xz + a_z + bz)) + 0.5f;
                float nn = tanhfast(xn + rr * (a_n + bn));
                stage[2 * w + l] = fmaf(zz, hold - nn, nn);
            }
            __syncthreads();

            // coalesced publish: 8 lanes x v4 store, then lane0 release-arrive
            {
                if (l < 8) {
                    float4 v = *(const float4*)&stage[4 * l];
                    uint32_t ra = ra_v + (p ? 0u : 2048u);   // dest buffer p^1
                    asm volatile("st.shared::cluster.v4.b32 [%0], {%1, %2, %3, %4};"
                                 :: "r"(ra),
                                    "r"(__float_as_uint(v.x)), "r"(__float_as_uint(v.y)),
                                    "r"(__float_as_uint(v.z)), "r"(__float_as_uint(v.w))
                                 : "memory");
                }
                __syncwarp();
                if (l == 0) {
                    uint32_t rm = p ? ra_a0 : ra_a1;
                    asm volatile("mbarrier.arrive.release.cluster.shared::cluster.b64 _, [%0];"
                                 :: "r"(rm) : "memory");
                }
            }
            p ^= 1;
            pending = true;
        }

        if (pending) {
            if (p == 0) {
                waitParityCluster(mb_s,      ph0);
                waitParityCluster(mb_s + 8,  ph0);
                ph0 ^= 1;
            } else {
                waitParityCluster(mb_s + 16, ph1);
                waitParityCluster(mb_s + 24, ph1);
                ph1 ^= 1;
            }
            pending = false;
        }
        if (tid < 32) {
            int j = 32 * (int)c + tid;
            out[b * H_ + j] = hb[p * 512 + hperm(j)];
        }
    }

    asm volatile("barrier.cluster.arrive.aligned;" ::: "memory");
    asm volatile("barrier.cluster.wait.aligned;"   ::: "memory");
}

// ================= fused kernel =================
__global__ void __launch_bounds__(512, 1)
fused_kernel(const float* __restrict__ visit_emb,
             const float* __restrict__ intervals,
             const float* __restrict__ W_time,
             const float* __restrict__ b_time,
             const float* __restrict__ W_ih,
             const float* __restrict__ W_hh,
             const float* __restrict__ b_ih,
             const float* __restrict__ b_hh,
             const int*   __restrict__ lens,
             float*       __restrict__ out)
{
    extern __shared__ char smc[];
    if (blockIdx.x >= SCAN_CTAS) {
        gemm_body(visit_emb, W_ih, intervals, W_time, b_time, b_ih, smc);
    } else {
        scan_body(W_hh, b_hh, lens, out, smc);
    }
}

// ---------------- launcher ----------------
extern "C" void kernel_launch(void* const* d_in, const int* in_sizes, int n_in,
                              void* d_out, int out_size)
{
    const float* visit_emb = (const float*)d_in[0];
    const float* intervals = (const float*)d_in[1];
    const float* W_time    = (const float*)d_in[2];
    const float* b_time    = (const float*)d_in[3];
    const float* W_ih      = (const float*)d_in[4];
    const float* W_hh      = (const float*)d_in[5];
    const float* b_ih      = (const float*)d_in[6];
    const float* b_hh      = (const float*)d_in[7];
    const int*   lens      = (const int*)d_in[8];
    float* out = (float*)d_out;

    void* readyPtr = nullptr;
    cudaGetSymbolAddress(&readyPtr, g_ready);
    cudaMemsetAsync(readyPtr, 0, 64 * sizeof(unsigned));

    cudaFuncSetAttribute(fused_kernel, cudaFuncAttributeNonPortableClusterSizeAllowed, 1);
    cudaFuncSetAttribute(fused_kernel, cudaFuncAttributeMaxDynamicSharedMemorySize, SCAN_SMEM);

    cudaLaunchConfig_t cfg = {};
    cfg.gridDim  = dim3(GRID_X, 1, 1);
    cfg.blockDim = dim3(512, 1, 1);
    cfg.dynamicSmemBytes = SCAN_SMEM;
    cfg.stream = 0;
    cudaLaunchAttribute attrs[1];
    attrs[0].id = cudaLaunchAttributeClusterDimension;
    attrs[0].val.clusterDim.x = 16;
    attrs[0].val.clusterDim.y = 1;
    attrs[0].val.clusterDim.z = 1;
    cfg.attrs = attrs;
    cfg.numAttrs = 1;

    cudaLaunchKernelEx(&cfg, fused_kernel,
                       visit_emb, intervals, W_time, b_time, W_ih, W_hh,
                       b_ih, b_hh, lens, out);
}

// round 10
// speedup vs baseline: 3.4046x; 1.0125x over previous
#include <cuda_runtime.h>
#include <cstdint>

#define B_   128
#define T_   64
#define V_   1024
#define TS_  64
#define H_   512
#define NTOK (B_ * T_)      // 8192
#define G3   (3 * H_)       // 1536
#define IN_  (V_ + TS_)     // 1088

typedef unsigned long long ull;

// ---------------- packed fp32x2 helpers (Blackwell) ----------------
__device__ __forceinline__ ull ffma2(ull a, ull b, ull c) {
    ull d;
    asm("fma.rn.f32x2 %0, %1, %2, %3;" : "=l"(d) : "l"(a), "l"(b), "l"(c));
    return d;
}
__device__ __forceinline__ ull dup2(float a) {
    ull d; unsigned u = __float_as_uint(a);
    asm("mov.b64 %0, {%1, %2};" : "=l"(d) : "r"(u), "r"(u));
    return d;
}
__device__ __forceinline__ float2 u2f(ull a) {
    float2 f; unsigned lo, hi;
    asm("mov.b64 {%0, %1}, %2;" : "=r"(lo), "=r"(hi) : "l"(a));
    f.x = __uint_as_float(lo); f.y = __uint_as_float(hi);
    return f;
}
__device__ __forceinline__ float tanhfast(float x) {
    float y; asm("tanh.approx.f32 %0, %1;" : "=f"(y) : "f"(x)); return y;
}

// ---------------- device scratch ----------------
__device__ float    g_xg[NTOK * G3];
__device__ unsigned g_ready[64];          // per 128-token row-tile: #col-tiles done

// ---------------- layout constants ----------------
#define SCAN_CTAS   16
#define GEMM_BLOCKS 768                   // 64 row-tiles x 12 col-tiles
#define GRID_X      (SCAN_CTAS + GEMM_BLOCKS)

#define BM 128
#define BN 128
#define BK 16
#define AST 132

// scan smem layout (dynamic): mbars | hb | stage | bhh | lens
#define SMEM_MBARS  0
#define SMEM_HB     32
#define SMEM_STAGE  (SMEM_HB + 4096)
#define SMEM_BHH    (SMEM_STAGE + 128)
#define SMEM_LENS   (SMEM_BHH + 384)
#define SCAN_BYTES  (SMEM_LENS + 512)
// gemm smem: As | Bs | caS | ccS
#define GEMM_BYTES  (2 * BK * AST * 4 + 2 * BN * 4)
#define DYN_SMEM    ((GEMM_BYTES > SCAN_BYTES ? GEMM_BYTES : SCAN_BYTES) + 128)

__device__ __forceinline__ int hperm(int col) {
    return ((col >> 2) & 3) * 128 + ((col >> 4) << 2) + (col & 3);
}

__device__ __forceinline__ void waitParityCluster(uint32_t addr, int ph) {
    asm volatile(
        "{\n\t"
        ".reg .pred p;\n\t"
        "WLOOP_%=:\n\t"
        "mbarrier.try_wait.parity.acquire.cluster.shared::cta.b64 p, [%0], %1, 0x989680;\n\t"
        "@p bra WDONE_%=;\n\t"
        "bra WLOOP_%=;\n\t"
        "WDONE_%=:\n\t"
        "}"
        :: "r"(addr), "r"(ph) : "memory");
}

// ================= GEMM body (blocks 16..783, 512 threads) =================
__device__ void gemm_body(const float* __restrict__ A,
                          const float* __restrict__ Bw,
                          const float* __restrict__ interval,
                          const float* __restrict__ W_time,
                          const float* __restrict__ b_time,
                          const float* __restrict__ b_ih,
                          char* smc)
{
    float (*As)[AST] = (float (*)[AST])smc;
    float (*Bs)[AST] = (float (*)[AST])(smc + BK * AST * 4);
    float* caS = (float*)(smc + 2 * BK * AST * 4);
    float* ccS = caS + BN;

    int tid = threadIdx.x;
    int gemmIdx = blockIdx.x - SCAN_CTAS;
    int rowTile = gemmIdx / 12;
    int colTile = gemmIdx - rowTile * 12;
    int rowBase = rowTile * BM;
    int colBase = colTile * BN;

    if (tid < BN) {
        int g = colBase + tid;
        const float* wrow = Bw + (size_t)g * IN_ + V_;
        float a = 0.f, cc = 0.f;
#pragma unroll 8
        for (int j = 0; j < TS_; j++) {
            float wv = wrow[j];
            a  += W_time[j] * wv;
            cc += b_time[j] * wv;
        }
        caS[tid] = a;
        ccS[tid] = cc + b_ih[g];
    }

    int tx = tid & 15;
    int ty = tid >> 4;
    int lr = tid >> 2;
    int kq = tid & 3;

    ull acc2[4][4];
#pragma unroll
    for (int i = 0; i < 4; i++)
#pragma unroll
        for (int j = 0; j < 4; j++) acc2[i][j] = 0ull;

    const float* Aptr = A  + (size_t)(rowBase + lr) * V_  + kq * 4;
    const float* Bptr = Bw + (size_t)(colBase + lr) * IN_ + kq * 4;

    for (int kt = 0; kt < V_; kt += BK) {
        float4 a0 = *(const float4*)(Aptr + kt);
        float4 b0 = *(const float4*)(Bptr + kt);

        __syncthreads();
        As[kq*4+0][lr] = a0.x; As[kq*4+1][lr] = a0.y; As[kq*4+2][lr] = a0.z; As[kq*4+3][lr] = a0.w;
        Bs[kq*4+0][lr] = b0.x; Bs[kq*4+1][lr] = b0.y; Bs[kq*4+2][lr] = b0.z; Bs[kq*4+3][lr] = b0.w;
        __syncthreads();

#pragma unroll
        for (int kk = 0; kk < BK; kk++) {
            float av[4];
            *(float4*)av = *(const float4*)&As[kk][ty*4];
            const ull* bp = (const ull*)&Bs[kk][tx*8];
            ull bv0 = bp[0], bv1 = bp[1], bv2 = bp[2], bv3 = bp[3];
#pragma unroll
            for (int i = 0; i < 4; i++) {
                ull a2 = dup2(av[i]);
                acc2[i][0] = ffma2(a2, bv0, acc2[i][0]);
                acc2[i][1] = ffma2(a2, bv1, acc2[i][1]);
                acc2[i][2] = ffma2(a2, bv2, acc2[i][2]);
                acc2[i][3] = ffma2(a2, bv3, acc2[i][3]);
            }
        }
    }

    float ai[4], ca[8], cc[8];
#pragma unroll
    for (int i = 0; i < 4; i++) ai[i] = interval[rowBase + ty*4 + i];
#pragma unroll
    for (int j = 0; j < 8; j++) {
        ca[j] = caS[tx*8 + j];
        cc[j] = ccS[tx*8 + j];
    }
#pragma unroll
    for (int i = 0; i < 4; i++) {
        size_t rbase = (size_t)(rowBase + ty*4 + i) * G3 + colBase + tx*8;
#pragma unroll
        for (int q = 0; q < 2; q++) {
            float2 v0 = u2f(acc2[i][2*q+0]);
            float2 v1 = u2f(acc2[i][2*q+1]);
            float4 o;
            o.x = v0.x + ai[i] * ca[4*q+0] + cc[4*q+0];
            o.y = v0.y + ai[i] * ca[4*q+1] + cc[4*q+1];
            o.z = v1.x + ai[i] * ca[4*q+2] + cc[4*q+2];
            o.w = v1.y + ai[i] * ca[4*q+3] + cc[4*q+3];
            *(float4*)&g_xg[rbase + 4*q] = o;
        }
    }

    __syncthreads();
    if (tid == 0) {
        __threadfence();
        atomicAdd(&g_ready[rowTile], 1u);
    }
}

// ================= scan body (blocks 0..15, one 16-CTA cluster) =================
// All 6 W_hh rows register-resident (96 regs/thread) — zero weight smem traffic.
// Elected-warp mbarrier wait (warps 0/1 wait one half each) + __syncthreads.
__device__ void scan_body(const float* __restrict__ W_hh,
                          const float* __restrict__ b_hh,
                          const int*   __restrict__ lens,
                          float*       __restrict__ out,
                          char* smc)
{
    float* hb      = (float*)(smc + SMEM_HB);
    float* stage   = (float*)(smc + SMEM_STAGE);
    float* bhh     = (float*)(smc + SMEM_BHH);
    int*   lens_sm = (int*)(smc + SMEM_LENS);
    uint32_t mb_s  = (uint32_t)__cvta_generic_to_shared(smc + SMEM_MBARS);

    int tid = threadIdx.x;
    int w = tid >> 5;
    int l = tid & 31;
    uint32_t c;
    asm("mov.u32 %0, %%cluster_ctarank;" : "=r"(c));

    hb[tid] = 0.f;
    hb[512 + tid] = 0.f;
    if (tid < 128) lens_sm[tid] = lens[tid];
    if (tid < 96) {
        int g = tid >> 5, u = tid & 31;
        bhh[tid] = b_hh[g * H_ + 32 * (int)c + u];
    }
    if (tid < 4) {
        asm volatile("mbarrier.init.shared.b64 [%0], 8;"
                     :: "r"(mb_s + 8u * tid) : "memory");
    }

    int j0 = 32 * (int)c + 2 * w;

    // all 6 rows (r0,r1,z0,z1,n0,n1) in registers as f32x2
    ull W2[6][8];
#pragma unroll
    for (int r = 0; r < 6; r++) {
        int row = (r < 2) ? (j0 + r) : (r < 4) ? (H_ + j0 + r - 2) : (2 * H_ + j0 + r - 4);
        const ull* wp = (const ull*)(W_hh + (size_t)row * H_ + 16 * l);
#pragma unroll
        for (int k = 0; k < 8; k++) W2[r][k] = wp[k];
    }
    __syncthreads();
    asm volatile("barrier.cluster.arrive.aligned;" ::: "memory");
    asm volatile("barrier.cluster.wait.aligned;"   ::: "memory");

    uint32_t hb_u = (uint32_t)__cvta_generic_to_shared(hb);
    // coalesced publish: lane g<8 ships stage[4g..4g+3] to CTA w as one v4
    uint32_t ra_v = 0;
    if (l < 8) {
        int slotbase = (l & 3) * 128 + (2 * (int)c + (l >> 2)) * 4;
        uint32_t la = hb_u + (uint32_t)(slotbase * 4);
        asm("mapa.shared::cluster.u32 %0, %1, %2;" : "=r"(ra_v) : "r"(la), "r"(w));
    }
    uint32_t ra_a0, ra_a1;
    {
        uint32_t lam0 = mb_s + 8u * (0u * 2u + (c & 1u));
        uint32_t lam1 = mb_s + 8u * (1u * 2u + (c & 1u));
        asm("mapa.shared::cluster.u32 %0, %1, %2;" : "=r"(ra_a0) : "r"(lam0), "r"(w));
        asm("mapa.shared::cluster.u32 %0, %1, %2;" : "=r"(ra_a1) : "r"(lam1), "r"(w));
    }

    int p = 0, ph0 = 0, ph1 = 0;
    bool pending = false;
    int cur_tile = -1;

    for (int b = 0; b < B_; b++) {
        int len = lens_sm[b];
        for (int t = 0; t < len; t++) {
            int n = (b << 6) + t;

            // wait until this token's GEMM row-tile is complete (12 col-tiles)
            if ((n >> 7) != cur_tile) {
                cur_tile = n >> 7;
                unsigned rdy;
                do {
                    asm volatile("ld.acquire.gpu.global.u32 %0, [%1];"
                                 : "=r"(rdy) : "l"(g_ready + cur_tile) : "memory");
                } while (rdy < 12u);
            }

            // xg loads issued before the sync wait
            float xr = 0.f, xz = 0.f, xn = 0.f;
            if (l < 2) {
                const float* xp = g_xg + (size_t)n * G3 + (j0 + l);
                xr = __ldg(xp);
                xz = __ldg(xp + H_);
                xn = __ldg(xp + 2 * H_);
            }

            // elected-warp wait: warps 0/1 wait one half-barrier each
            if (pending) {
                if (w < 2) {
                    uint32_t a = mb_s + (p ? 16u : 0u) + 8u * (uint32_t)w;
                    waitParityCluster(a, p ? ph1 : ph0);
                }
                __syncthreads();
                if (p == 0) ph0 ^= 1; else ph1 ^= 1;
                pending = false;
            }

            const float* hp = hb + p * 512;
            float hold = 0.f;
            if (l < 2) hold = hp[hperm(j0 + l)];

            ull acc2[6] = {0ull, 0ull, 0ull, 0ull, 0ull, 0ull};
#pragma unroll
            for (int qq = 0; qq < 4; qq++) {
                const ull* hq = (const ull*)(hp + qq * 128 + l * 4);
                ull h01 = hq[0], h23 = hq[1];
#pragma unroll
                for (int r = 0; r < 6; r++) acc2[r] = ffma2(W2[r][2*qq+0], h01, acc2[r]);
#pragma unroll
                for (int r = 0; r < 6; r++) acc2[r] = ffma2(W2[r][2*qq+1], h23, acc2[r]);
            }
            float acc[6];
#pragma unroll
            for (int r = 0; r < 6; r++) { float2 f = u2f(acc2[r]); acc[r] = f.x + f.y; }

            // split-butterfly reduce: 6 + 12 + 3 SHFLs
#pragma unroll
            for (int r = 0; r < 6; r++)
                acc[r] += __shfl_xor_sync(0xffffffffu, acc[r], 16);
            bool hihalf = (l >= 16);
            float s0 = hihalf ? acc[3] : acc[0];
            float s1 = hihalf ? acc[4] : acc[1];
            float s2 = hihalf ? acc[5] : acc[2];
#pragma unroll
            for (int off = 8; off > 0; off >>= 1) {
                s0 += __shfl_xor_sync(0xffffffffu, s0, off);
                s1 += __shfl_xor_sync(0xffffffffu, s1, off);
                s2 += __shfl_xor_sync(0xffffffffu, s2, off);
            }
            float t0 = __shfl_sync(0xffffffffu, s0, 16);   // acc3
            float t1 = __shfl_sync(0xffffffffu, s1, 16);   // acc4
            float t2 = __shfl_sync(0xffffffffu, s2, 16);   // acc5

            if (l < 2) {
                int bidx = 2 * w + l;
                float a_r = l ? s1 : s0;
                float a_z = l ? t0 : s2;
                float a_n = l ? t2 : t1;
                float rr = 0.5f * tanhfast(0.5f * (xr + a_r + bhh[bidx]))      + 0.5f;
                float zz = 0.5f * tanhfast(0.5f * (xz + a_z + bhh[32 + bidx])) + 0.5f;
                float nn = tanhfast(xn + rr * (a_n + bhh[64 + bidx]));
                stage[bidx] = fmaf(zz, hold - nn, nn);
            }
            __syncthreads();

            // coalesced publish: 8 lanes x v4 store, then lane0 release-arrive
            {
                if (l < 8) {
                    float4 v = *(const float4*)&stage[4 * l];
                    uint32_t ra = ra_v + (p ? 0u : 2048u);   // dest buffer p^1
                    asm volatile("st.shared::cluster.v4.b32 [%0], {%1, %2, %3, %4};"
                                 :: "r"(ra),
                                    "r"(__float_as_uint(v.x)), "r"(__float_as_uint(v.y)),
                                    "r"(__float_as_uint(v.z)), "r"(__float_as_uint(v.w))
                                 : "memory");
                }
                __syncwarp();
                if (l == 0) {
                    uint32_t rm = p ? ra_a0 : ra_a1;
                    asm volatile("mbarrier.arrive.release.cluster.shared::cluster.b64 _, [%0];"
                                 :: "r"(rm) : "memory");
                }
            }
            p ^= 1;
            pending = true;
        }

        if (pending) {
            if (w < 2) {
                uint32_t a = mb_s + (p ? 16u : 0u) + 8u * (uint32_t)w;
                waitParityCluster(a, p ? ph1 : ph0);
            }
            __syncthreads();
            if (p == 0) ph0 ^= 1; else ph1 ^= 1;
            pending = false;
        }
        if (tid < 32) {
            int j = 32 * (int)c + tid;
            out[b * H_ + j] = hb[p * 512 + hperm(j)];
        }
    }

    asm volatile("barrier.cluster.arrive.aligned;" ::: "memory");
    asm volatile("barrier.cluster.wait.aligned;"   ::: "memory");
}

// ================= fused kernel =================
__global__ void __launch_bounds__(512, 1)
fused_kernel(const float* __restrict__ visit_emb,
             const float* __restrict__ intervals,
             const float* __restrict__ W_time,
             const float* __restrict__ b_time,
             const float* __restrict__ W_ih,
             const float* __restrict__ W_hh,
             const float* __restrict__ b_ih,
             const float* __restrict__ b_hh,
             const int*   __restrict__ lens,
             float*       __restrict__ out)
{
    extern __shared__ char smc[];
    if (blockIdx.x >= SCAN_CTAS) {
        gemm_body(visit_emb, W_ih, intervals, W_time, b_time, b_ih, smc);
    } else {
        scan_body(W_hh, b_hh, lens, out, smc);
    }
}

// ---------------- launcher ----------------
extern "C" void kernel_launch(void* const* d_in, const int* in_sizes, int n_in,
                              void* d_out, int out_size)
{
    const float* visit_emb = (const float*)d_in[0];
    const float* intervals = (const float*)d_in[1];
    const float* W_time    = (const float*)d_in[2];
    const float* b_time    = (const float*)d_in[3];
    const float* W_ih      = (const float*)d_in[4];
    const float* W_hh      = (const float*)d_in[5];
    const float* b_ih      = (const float*)d_in[6];
    const float* b_hh      = (const float*)d_in[7];
    const int*   lens      = (const int*)d_in[8];
    float* out = (float*)d_out;

    void* readyPtr = nullptr;
    cudaGetSymbolAddress(&readyPtr, g_ready);
    cudaMemsetAsync(readyPtr, 0, 64 * sizeof(unsigned));

    cudaFuncSetAttribute(fused_kernel, cudaFuncAttributeNonPortableClusterSizeAllowed, 1);
    cudaFuncSetAttribute(fused_kernel, cudaFuncAttributeMaxDynamicSharedMemorySize, DYN_SMEM);

    cudaLaunchConfig_t cfg = {};
    cfg.gridDim  = dim3(GRID_X, 1, 1);
    cfg.blockDim = dim3(512, 1, 1);
    cfg.dynamicSmemBytes = DYN_SMEM;
    cfg.stream = 0;
    cudaLaunchAttribute attrs[1];
    attrs[0].id = cudaLaunchAttributeClusterDimension;
    attrs[0].val.clusterDim.x = 16;
    attrs[0].val.clusterDim.y = 1;
    attrs[0].val.clusterDim.z = 1;
    cfg.attrs = attrs;
    cfg.numAttrs = 1;

    cudaLaunchKernelEx(&cfg, fused_kernel,
                       visit_emb, intervals, W_time, b_time, W_ih, W_hh,
                       b_ih, b_hh, lens, out);
}

// round 11
// speedup vs baseline: 4.6724x; 1.3724x over previous
#include <cuda_runtime.h>
#include <cstdint>

#define B_   128
#define T_   64
#define V_   1024
#define TS_  64
#define H_   512
#define NTOK (B_ * T_)      // 8192
#define G3   (3 * H_)       // 1536
#define IN_  (V_ + TS_)     // 1088

typedef unsigned long long ull;

// ---------------- packed fp32x2 helpers (Blackwell) ----------------
__device__ __forceinline__ ull ffma2(ull a, ull b, ull c) {
    ull d;
    asm("fma.rn.f32x2 %0, %1, %2, %3;" : "=l"(d) : "l"(a), "l"(b), "l"(c));
    return d;
}
__device__ __forceinline__ ull dup2(float a) {
    ull d; unsigned u = __float_as_uint(a);
    asm("mov.b64 %0, {%1, %2};" : "=l"(d) : "r"(u), "r"(u));
    return d;
}
__device__ __forceinline__ float2 u2f(ull a) {
    float2 f; unsigned lo, hi;
    asm("mov.b64 {%0, %1}, %2;" : "=r"(lo), "=r"(hi) : "l"(a));
    f.x = __uint_as_float(lo); f.y = __uint_as_float(hi);
    return f;
}
__device__ __forceinline__ float tanhfast(float x) {
    float y; asm("tanh.approx.f32 %0, %1;" : "=f"(y) : "f"(x)); return y;
}

// ---------------- device scratch ----------------
__device__ float    g_xg[NTOK * G3];
__device__ unsigned g_ready[64];          // per 128-token row-tile: #col-tiles done

// ---------------- layout constants ----------------
#define SCAN_CTAS   16
#define GEMM_BLOCKS 768                   // 64 row-tiles x 12 col-tiles
#define GRID_X      (SCAN_CTAS + GEMM_BLOCKS)

#define BM 128
#define BN 128
#define BK 16
#define AST 132

// scan smem layout (dynamic): mbars | hb | stage | bhh | lens
#define SMEM_MBARS  0
#define SMEM_HB     32
#define SMEM_STAGE  (SMEM_HB + 4096)
#define SMEM_BHH    (SMEM_STAGE + 128)
#define SMEM_LENS   (SMEM_BHH + 384)
#define SCAN_BYTES  (SMEM_LENS + 512)
// gemm smem: As | Bs | caS | ccS
#define GEMM_BYTES  (2 * BK * AST * 4 + 2 * BN * 4)
#define DYN_SMEM    ((GEMM_BYTES > SCAN_BYTES ? GEMM_BYTES : SCAN_BYTES) + 128)

// per-phase expected bytes at each dest barrier:
// 16 src CTAs x 16 lanes x 8B = 2048
#define TX_BYTES 2048u

__device__ __forceinline__ int hperm(int col) {
    return ((col >> 2) & 3) * 128 + ((col >> 4) << 2) + (col & 3);
}

__device__ __forceinline__ void waitParityCluster(uint32_t addr, int ph) {
    asm volatile(
        "{\n\t"
        ".reg .pred p;\n\t"
        "WLOOP_%=:\n\t"
        "mbarrier.try_wait.parity.acquire.cluster.shared::cta.b64 p, [%0], %1, 0x989680;\n\t"
        "@p bra WDONE_%=;\n\t"
        "bra WLOOP_%=;\n\t"
        "WDONE_%=:\n\t"
        "}"
        :: "r"(addr), "r"(ph) : "memory");
}

// ================= GEMM body (blocks 16..783, 512 threads) =================
__device__ void gemm_body(const float* __restrict__ A,
                          const float* __restrict__ Bw,
                          const float* __restrict__ interval,
                          const float* __restrict__ W_time,
                          const float* __restrict__ b_time,
                          const float* __restrict__ b_ih,
                          char* smc)
{
    float (*As)[AST] = (float (*)[AST])smc;
    float (*Bs)[AST] = (float (*)[AST])(smc + BK * AST * 4);
    float* caS = (float*)(smc + 2 * BK * AST * 4);
    float* ccS = caS + BN;

    int tid = threadIdx.x;
    int gemmIdx = blockIdx.x - SCAN_CTAS;
    int rowTile = gemmIdx / 12;
    int colTile = gemmIdx - rowTile * 12;
    int rowBase = rowTile * BM;
    int colBase = colTile * BN;

    if (tid < BN) {
        int g = colBase + tid;
        const float* wrow = Bw + (size_t)g * IN_ + V_;
        float a = 0.f, cc = 0.f;
#pragma unroll 8
        for (int j = 0; j < TS_; j++) {
            float wv = wrow[j];
            a  += W_time[j] * wv;
            cc += b_time[j] * wv;
        }
        caS[tid] = a;
        ccS[tid] = cc + b_ih[g];
    }

    int tx = tid & 15;
    int ty = tid >> 4;
    int lr = tid >> 2;
    int kq = tid & 3;

    ull acc2[4][4];
#pragma unroll
    for (int i = 0; i < 4; i++)
#pragma unroll
        for (int j = 0; j < 4; j++) acc2[i][j] = 0ull;

    const float* Aptr = A  + (size_t)(rowBase + lr) * V_  + kq * 4;
    const float* Bptr = Bw + (size_t)(colBase + lr) * IN_ + kq * 4;

    for (int kt = 0; kt < V_; kt += BK) {
        float4 a0 = *(const float4*)(Aptr + kt);
        float4 b0 = *(const float4*)(Bptr + kt);

        __syncthreads();
        As[kq*4+0][lr] = a0.x; As[kq*4+1][lr] = a0.y; As[kq*4+2][lr] = a0.z; As[kq*4+3][lr] = a0.w;
        Bs[kq*4+0][lr] = b0.x; Bs[kq*4+1][lr] = b0.y; Bs[kq*4+2][lr] = b0.z; Bs[kq*4+3][lr] = b0.w;
        __syncthreads();

#pragma unroll
        for (int kk = 0; kk < BK; kk++) {
            float av[4];
            *(float4*)av = *(const float4*)&As[kk][ty*4];
            const ull* bp = (const ull*)&Bs[kk][tx*8];
            ull bv0 = bp[0], bv1 = bp[1], bv2 = bp[2], bv3 = bp[3];
#pragma unroll
            for (int i = 0; i < 4; i++) {
                ull a2 = dup2(av[i]);
                acc2[i][0] = ffma2(a2, bv0, acc2[i][0]);
                acc2[i][1] = ffma2(a2, bv1, acc2[i][1]);
                acc2[i][2] = ffma2(a2, bv2, acc2[i][2]);
                acc2[i][3] = ffma2(a2, bv3, acc2[i][3]);
            }
        }
    }

    float ai[4], ca[8], cc[8];
#pragma unroll
    for (int i = 0; i < 4; i++) ai[i] = interval[rowBase + ty*4 + i];
#pragma unroll
    for (int j = 0; j < 8; j++) {
        ca[j] = caS[tx*8 + j];
        cc[j] = ccS[tx*8 + j];
    }
#pragma unroll
    for (int i = 0; i < 4; i++) {
        size_t rbase = (size_t)(rowBase + ty*4 + i) * G3 + colBase + tx*8;
#pragma unroll
        for (int q = 0; q < 2; q++) {
            float2 v0 = u2f(acc2[i][2*q+0]);
            float2 v1 = u2f(acc2[i][2*q+1]);
            float4 o;
            o.x = v0.x + ai[i] * ca[4*q+0] + cc[4*q+0];
            o.y = v0.y + ai[i] * ca[4*q+1] + cc[4*q+1];
            o.z = v1.x + ai[i] * ca[4*q+2] + cc[4*q+2];
            o.w = v1.y + ai[i] * ca[4*q+3] + cc[4*q+3];
            *(float4*)&g_xg[rbase + 4*q] = o;
        }
    }

    __syncthreads();
    if (tid == 0) {
        __threadfence();
        atomicAdd(&g_ready[rowTile], 1u);
    }
}

// ================= scan body (blocks 0..15, one 16-CTA cluster) =================
// Sync redesign: producers publish with st.async (data + tx-bytes completion in
// ONE flight to the dest barrier); consumers try_wait a local barrier armed via
// arrive.expect_tx(2048) one full step ahead. No arrive flights, no arrive
// ATOMS serialization, no source-side release, no pre-matvec __syncthreads.
__device__ void scan_body(const float* __restrict__ W_hh,
                          const float* __restrict__ b_hh,
                          const int*   __restrict__ lens,
                          float*       __restrict__ out,
                          char* smc)
{
    float* hb      = (float*)(smc + SMEM_HB);
    float* stage   = (float*)(smc + SMEM_STAGE);
    float* bhh     = (float*)(smc + SMEM_BHH);
    int*   lens_sm = (int*)(smc + SMEM_LENS);
    uint32_t mb_s  = (uint32_t)__cvta_generic_to_shared(smc + SMEM_MBARS);

    int tid = threadIdx.x;
    int w = tid >> 5;
    int l = tid & 31;
    uint32_t c;
    asm("mov.u32 %0, %%cluster_ctarank;" : "=r"(c));

    hb[tid] = 0.f;
    hb[512 + tid] = 0.f;
    if (tid < 128) lens_sm[tid] = lens[tid];
    if (tid < 96) {
        int g = tid >> 5, u = tid & 31;
        bhh[tid] = b_hh[g * H_ + 32 * (int)c + u];
    }
    if (tid == 0) {
        // bar[0] at mb_s, bar[1] at mb_s+8; arrive count 1 (the re-armer)
        asm volatile("mbarrier.init.shared.b64 [%0], 1;" :: "r"(mb_s)      : "memory");
        asm volatile("mbarrier.init.shared.b64 [%0], 1;" :: "r"(mb_s + 8) : "memory");
        // arm phase 0 of both barriers before any tx can arrive
        asm volatile("mbarrier.arrive.expect_tx.shared.b64 _, [%0], %1;"
                     :: "r"(mb_s),     "r"(TX_BYTES) : "memory");
        asm volatile("mbarrier.arrive.expect_tx.shared.b64 _, [%0], %1;"
                     :: "r"(mb_s + 8), "r"(TX_BYTES) : "memory");
        asm volatile("fence.mbarrier_init.release.cluster;" ::: "memory");
    }

    int j0 = 32 * (int)c + 2 * w;

    // all 6 W_hh rows (r0,r1,z0,z1,n0,n1) register-resident as f32x2
    ull W2[6][8];
#pragma unroll
    for (int r = 0; r < 6; r++) {
        int row = (r < 2) ? (j0 + r) : (r < 4) ? (H_ + j0 + r - 2) : (2 * H_ + j0 + r - 4);
        const ull* wp = (const ull*)(W_hh + (size_t)row * H_ + 16 * l);
#pragma unroll
        for (int k = 0; k < 8; k++) W2[r][k] = wp[k];
    }
    __syncthreads();
    asm volatile("barrier.cluster.arrive.aligned;" ::: "memory");
    asm volatile("barrier.cluster.wait.aligned;"   ::: "memory");

    uint32_t hb_u = (uint32_t)__cvta_generic_to_shared(hb);
    // publish addresses: warp w ships this CTA's 32 units to CTA w.
    // lane l<16 carries pair (2l, 2l+1) as one b64 (hperm maps aligned pairs
    // to adjacent, 8B-aligned slots).
    uint32_t ra_pair = 0, rb_bar0 = 0, rb_bar1 = 0;
    if (l < 16) {
        uint32_t la = hb_u + (uint32_t)(hperm(32 * (int)c + 2 * l) * 4);
        asm("mapa.shared::cluster.u32 %0, %1, %2;" : "=r"(ra_pair) : "r"(la), "r"(w));
        asm("mapa.shared::cluster.u32 %0, %1, %2;" : "=r"(rb_bar0) : "r"(mb_s),     "r"(w));
        asm("mapa.shared::cluster.u32 %0, %1, %2;" : "=r"(rb_bar1) : "r"(mb_s + 8), "r"(w));
    }

    int p = 0, ph0 = 0, ph1 = 0;
    bool pending = false;
    int cur_tile = -1;

    for (int b = 0; b < B_; b++) {
        int len = lens_sm[b];
        for (int t = 0; t < len; t++) {
            int n = (b << 6) + t;

            // wait until this token's GEMM row-tile is complete (12 col-tiles)
            if ((n >> 7) != cur_tile) {
                cur_tile = n >> 7;
                unsigned rdy;
                do {
                    asm volatile("ld.acquire.gpu.global.u32 %0, [%1];"
                                 : "=r"(rdy) : "l"(g_ready + cur_tile) : "memory");
                } while (rdy < 12u);
            }

            // xg loads issued before the sync wait
            float xr = 0.f, xz = 0.f, xn = 0.f;
            if (l < 2) {
                const float* xp = g_xg + (size_t)n * G3 + (j0 + l);
                xr = __ldg(xp);
                xz = __ldg(xp + H_);
                xn = __ldg(xp + 2 * H_);
            }

            // every warp waits the local barrier directly (no BAR); thread 0
            // re-arms the barrier for its next use (2 steps away -> huge margin)
            if (pending) {
                uint32_t a = mb_s + 8u * (uint32_t)p;
                waitParityCluster(a, p ? ph1 : ph0);
                if (tid == 0)
                    asm volatile("mbarrier.arrive.expect_tx.shared.b64 _, [%0], %1;"
                                 :: "r"(a), "r"(TX_BYTES) : "memory");
                if (p) ph1 ^= 1; else ph0 ^= 1;
                pending = false;
            }

            const float* hp = hb + p * 512;
            float hold = 0.f;
            if (l < 2) hold = hp[hperm(j0 + l)];

            ull acc2[6] = {0ull, 0ull, 0ull, 0ull, 0ull, 0ull};
#pragma unroll
            for (int qq = 0; qq < 4; qq++) {
                const ull* hq = (const ull*)(hp + qq * 128 + l * 4);
                ull h01 = hq[0], h23 = hq[1];
#pragma unroll
                for (int r = 0; r < 6; r++) acc2[r] = ffma2(W2[r][2*qq+0], h01, acc2[r]);
#pragma unroll
                for (int r = 0; r < 6; r++) acc2[r] = ffma2(W2[r][2*qq+1], h23, acc2[r]);
            }
            float acc[6];
#pragma unroll
            for (int r = 0; r < 6; r++) { float2 f = u2f(acc2[r]); acc[r] = f.x + f.y; }

            // split-butterfly reduce: 6 + 12 + 3 SHFLs
#pragma unroll
            for (int r = 0; r < 6; r++)
                acc[r] += __shfl_xor_sync(0xffffffffu, acc[r], 16);
            bool hihalf = (l >= 16);
            float s0 = hihalf ? acc[3] : acc[0];
            float s1 = hihalf ? acc[4] : acc[1];
            float s2 = hihalf ? acc[5] : acc[2];
#pragma unroll
            for (int off = 8; off > 0; off >>= 1) {
                s0 += __shfl_xor_sync(0xffffffffu, s0, off);
                s1 += __shfl_xor_sync(0xffffffffu, s1, off);
                s2 += __shfl_xor_sync(0xffffffffu, s2, off);
            }
            float t0 = __shfl_sync(0xffffffffu, s0, 16);   // acc3
            float t1 = __shfl_sync(0xffffffffu, s1, 16);   // acc4
            float t2 = __shfl_sync(0xffffffffu, s2, 16);   // acc5

            if (l < 2) {
                int bidx = 2 * w + l;
                float a_r = l ? s1 : s0;
                float a_z = l ? t0 : s2;
                float a_n = l ? t2 : t1;
                float rr = 0.5f * tanhfast(0.5f * (xr + a_r + bhh[bidx]))      + 0.5f;
                float zz = 0.5f * tanhfast(0.5f * (xz + a_z + bhh[32 + bidx])) + 0.5f;
                float nn = tanhfast(xn + rr * (a_n + bhh[64 + bidx]));
                stage[bidx] = fmaf(zz, hold - nn, nn);
            }
            __syncthreads();   // stage ready; also fences all local reads of hb[p^1]

            // single-flight publish: data + tx completion in one st.async
            if (l < 16) {
                ull v = *(const ull*)&stage[2 * l];
                uint32_t ra = ra_pair + (p ? 0u : 2048u);   // dest buffer p^1
                uint32_t rb = p ? rb_bar0 : rb_bar1;        // bar[p^1]
                asm volatile(
                    "st.async.shared::cluster.mbarrier::complete_tx::bytes.b64 [%0], %1, [%2];"
                    :: "r"(ra), "l"(v), "r"(rb) : "memory");
            }
            p ^= 1;
            pending = true;
        }

        if (pending) {
            uint32_t a = mb_s + 8u * (uint32_t)p;
            waitParityCluster(a, p ? ph1 : ph0);
            if (tid == 0)
                asm volatile("mbarrier.arrive.expect_tx.shared.b64 _, [%0], %1;"
                             :: "r"(a), "r"(TX_BYTES) : "memory");
            if (p) ph1 ^= 1; else ph0 ^= 1;
            pending = false;
        }
        if (tid < 32) {
            int j = 32 * (int)c + tid;
            out[b * H_ + j] = hb[p * 512 + hperm(j)];
        }
    }

    asm volatile("barrier.cluster.arrive.aligned;" ::: "memory");
    asm volatile("barrier.cluster.wait.aligned;"   ::: "memory");
}

// ================= fused kernel =================
__global__ void __launch_bounds__(512, 1)
fused_kernel(const float* __restrict__ visit_emb,
             const float* __restrict__ intervals,
             const float* __restrict__ W_time,
             const float* __restrict__ b_time,
             const float* __restrict__ W_ih,
             const float* __restrict__ W_hh,
             const float* __restrict__ b_ih,
             const float* __restrict__ b_hh,
             const int*   __restrict__ lens,
             float*       __restrict__ out)
{
    extern __shared__ char smc[];
    if (blockIdx.x >= SCAN_CTAS) {
        gemm_body(visit_emb, W_ih, intervals, W_time, b_time, b_ih, smc);
    } else {
        scan_body(W_hh, b_hh, lens, out, smc);
    }
}

// ---------------- launcher ----------------
extern "C" void kernel_launch(void* const* d_in, const int* in_sizes, int n_in,
                              void* d_out, int out_size)
{
    const float* visit_emb = (const float*)d_in[0];
    const float* intervals = (const float*)d_in[1];
    const float* W_time    = (const float*)d_in[2];
    const float* b_time    = (const float*)d_in[3];
    const float* W_ih      = (const float*)d_in[4];
    const float* W_hh      = (const float*)d_in[5];
    const float* b_ih      = (const float*)d_in[6];
    const float* b_hh      = (const float*)d_in[7];
    const int*   lens      = (const int*)d_in[8];
    float* out = (float*)d_out;

    void* readyPtr = nullptr;
    cudaGetSymbolAddress(&readyPtr, g_ready);
    cudaMemsetAsync(readyPtr, 0, 64 * sizeof(unsigned));

    cudaFuncSetAttribute(fused_kernel, cudaFuncAttributeNonPortableClusterSizeAllowed, 1);
    cudaFuncSetAttribute(fused_kernel, cudaFuncAttributeMaxDynamicSharedMemorySize, DYN_SMEM);

    cudaLaunchConfig_t cfg = {};
    cfg.gridDim  = dim3(GRID_X, 1, 1);
    cfg.blockDim = dim3(512, 1, 1);
    cfg.dynamicSmemBytes = DYN_SMEM;
    cfg.stream = 0;
    cudaLaunchAttribute attrs[1];
    attrs[0].id = cudaLaunchAttributeClusterDimension;
    attrs[0].val.clusterDim.x = 16;
    attrs[0].val.clusterDim.y = 1;
    attrs[0].val.clusterDim.z = 1;
    cfg.attrs = attrs;
    cfg.numAttrs = 1;

    cudaLaunchKernelEx(&cfg, fused_kernel,
                       visit_emb, intervals, W_time, b_time, W_ih, W_hh,
                       b_ih, b_hh, lens, out);
}